// round 6
// baseline (speedup 1.0000x reference)
#include <cuda_runtime.h>
#include <cstdint>
#include <cstdio>

// ---------------------------------------------------------------------------
// LiBNet forward, batch 512.  Round 6: dp2a register-windowed grouped convs,
// bn_sign fused into gemm tile loaders, self-staged weights, 14 launches.
// ---------------------------------------------------------------------------

#define BATCH 512

__device__ float   g_y1[512u*1024u*64u];   // conv1 out  [b,32,32,64] fp32
__device__ int8_t  g_a1[512u*256u*64u];    // sign(pool(bn1)) [b,16,16,64]
__device__ int8_t  g_y2b[512u*256u*64u];   // conv2_1 out int8
__device__ int8_t  g_y3b[512u*256u*256u];  // conv2_2 out int8
__device__ int8_t  g_a3[512u*64u*256u];    // sign(pool(bn2_2)) [b,8,8,256]
__device__ int8_t  g_y4b[512u*64u*256u];   // conv3_1 out int8
__device__ int16_t g_y5s[512u*64u*256u];   // conv3_2 out int16
__device__ int8_t  g_wp2[256*64];          // sign(w2_2)
__device__ int8_t  g_wp3[256*256];         // sign(w3_2)
__device__ float   g_part[2097152];        // stats partials [c][slice]
__device__ float   g_mean[256];
__device__ float   g_scale[256];
__device__ float   g_fcwr[16384*10];       // fc_w n-major over NHWC-flatten

__device__ __forceinline__ int dp2a_lo(int a, int b, int c) {
    int d;
    asm("dp2a.lo.s32.s32 %0, %1, %2, %3;" : "=r"(d) : "r"(a), "r"(b), "r"(c));
    return d;
}

// ---------------------------------------------------------------------------
// conv1: x [b,3,32,32] NCHW, pad (t1,b2,l1,r2), out NHWC [b,32,32,64] fp32.
// 8 output rows per block; self-staged binarized weights (conflict-free
// 65-padded smem transpose); fused channel stats.
// block: 256 = (c 0..63, xq 0..3); grid (4, B).
// ---------------------------------------------------------------------------
__global__ void conv1_kernel(const float* __restrict__ x,
                             const float* __restrict__ w1,
                             float* __restrict__ y1) {
    const int NS = 2048;  // 4 * 512 slices
    int b = blockIdx.y, oy0 = blockIdx.x * 8;
    int tid = threadIdx.x;
    int c = tid & 63, xq = tid >> 6;

    __shared__ float xs[3][11][36];   // rows iy = oy0-1 .. oy0+9
    __shared__ float wt[48 * 65];     // [k][c] padded row 65 (conflict-free)
    __shared__ float2 sred[256];

    // stage + binarize + transpose w1 (coalesced reads, conflict-free writes)
    for (int i = tid; i < 3072; i += 256) {
        int cc = i / 48, k = i % 48;
        float v = w1[i];
        wt[k * 65 + cc] = (v > 0.f) ? 1.f : ((v < 0.f) ? -1.f : 0.f);
    }
    for (int i = tid; i < 3 * 11 * 36; i += 256) {
        int col = i % 36;
        int r   = (i / 36) % 11;
        int ci  = i / 396;
        int ix = col - 1, iy = oy0 - 1 + r;
        float v = 0.f;
        if (ix >= 0 && ix < 32 && iy >= 0 && iy < 32)
            v = x[(((size_t)b * 3 + ci) * 32 + iy) * 32 + ix];
        xs[ci][r][col] = v;
    }
    __syncthreads();

    float wr[48];
#pragma unroll
    for (int k = 0; k < 48; k++) wr[k] = wt[k * 65 + c];

    float s1 = 0.f, s2 = 0.f;
#pragma unroll
    for (int r = 0; r < 8; r++) {
        float acc[8];
#pragma unroll
        for (int j = 0; j < 8; j++) acc[j] = 0.f;
#pragma unroll
        for (int ci = 0; ci < 3; ci++) {
#pragma unroll
            for (int kh = 0; kh < 4; kh++) {
                float rx[11];
#pragma unroll
                for (int t = 0; t < 11; t++) rx[t] = xs[ci][r + kh][xq * 8 + t];
#pragma unroll
                for (int kw = 0; kw < 4; kw++) {
                    float wv = wr[ci * 16 + kh * 4 + kw];
#pragma unroll
                    for (int j = 0; j < 8; j++) acc[j] += wv * rx[j + kw];
                }
            }
        }
        size_t obase = (((size_t)b * 32 + oy0 + r) * 32 + xq * 8) * 64 + c;
#pragma unroll
        for (int j = 0; j < 8; j++) {
            y1[obase + (size_t)j * 64] = acc[j];
            s1 += acc[j];
            s2 += acc[j] * acc[j];
        }
    }

    sred[tid] = make_float2(s1, s2);
    __syncthreads();
    if (tid < 64) {
        float2 a = sred[tid], b1 = sred[tid + 64], c1 = sred[tid + 128],
               d1 = sred[tid + 192];
        int slice = b * 4 + blockIdx.x;
        g_part[tid * NS + slice]        = a.x + b1.x + c1.x + d1.x;
        g_part[(64 + tid) * NS + slice] = a.y + b1.y + c1.y + d1.y;
    }
}

// ---------------------------------------------------------------------------
// Reduce partials ([c][slice], coalesced) + shift-BN finalize.
// ---------------------------------------------------------------------------
template <int C>
__global__ void reduce_finalize_kernel(const float* __restrict__ gamma,
                                       int nslices, int P) {
    int c = blockIdx.x;
    int tid = threadIdx.x;
    float s1 = 0.f, s2 = 0.f;
    const float* p1 = g_part + (size_t)c * nslices;
    const float* p2 = g_part + (size_t)(C + c) * nslices;
#pragma unroll 4
    for (int s = tid; s < nslices; s += 256) {
        s1 += p1[s];
        s2 += p2[s];
    }
    __shared__ double sd1[256], sd2[256];
    sd1[tid] = (double)s1;
    sd2[tid] = (double)s2;
    __syncthreads();
    for (int s = 128; s > 0; s >>= 1) {
        if (tid < s) {
            sd1[tid] += sd1[tid + s];
            sd2[tid] += sd2[tid + s];
        }
        __syncthreads();
    }
    if (tid == 0) {
        double mean = sd1[0] / (double)P;
        double var  = sd2[0] / (double)P - mean * mean;
        double inv  = (double)gamma[c] / sqrt(var + 1e-5);
        double sh   = rint(log2(fabs(inv) + 1e-12));
        if (sh > 4.0) sh = 4.0;
        if (sh < -4.0) sh = -4.0;
        double sgn = (inv > 0.0) ? 1.0 : ((inv < 0.0) ? -1.0 : 0.0);
        g_mean[c]  = (float)mean;
        g_scale[c] = (float)(sgn * exp2(sh));
    }
}

// ---------------------------------------------------------------------------
// BN + 2x2 maxpool + sign, fp32 input (stage 1). 4 ch/thread.
// ---------------------------------------------------------------------------
template <int H, int C>
__global__ void bn_pool_sign4_f_kernel(const float* __restrict__ y,
                                       int8_t* __restrict__ out,
                                       const float* __restrict__ beta,
                                       int total4) {
    int idx = blockIdx.x * 256 + threadIdx.x;
    if (idx >= total4) return;
    constexpr int Ho = H / 2;
    int e = idx * 4;
    int c = e % C;
    int t = e / C;
    int ox = t % Ho; t /= Ho;
    int oy = t % Ho;
    int b  = t / Ho;
    float4 m  = *(const float4*)(g_mean + c);
    float4 s  = *(const float4*)(g_scale + c);
    float4 bt = *(const float4*)(beta + c);
    size_t base = (((size_t)b * H + 2 * oy) * H + 2 * ox) * C + c;
    float4 v0 = *(const float4*)(y + base);
    float4 v1 = *(const float4*)(y + base + C);
    float4 v2 = *(const float4*)(y + base + (size_t)H * C);
    float4 v3 = *(const float4*)(y + base + (size_t)H * C + C);
    float r0 = fmaxf(fmaxf((v0.x - m.x) * s.x, (v1.x - m.x) * s.x),
                     fmaxf((v2.x - m.x) * s.x, (v3.x - m.x) * s.x)) + bt.x;
    float r1 = fmaxf(fmaxf((v0.y - m.y) * s.y, (v1.y - m.y) * s.y),
                     fmaxf((v2.y - m.y) * s.y, (v3.y - m.y) * s.y)) + bt.y;
    float r2 = fmaxf(fmaxf((v0.z - m.z) * s.z, (v1.z - m.z) * s.z),
                     fmaxf((v2.z - m.z) * s.z, (v3.z - m.z) * s.z)) + bt.z;
    float r3 = fmaxf(fmaxf((v0.w - m.w) * s.w, (v1.w - m.w) * s.w),
                     fmaxf((v2.w - m.w) * s.w, (v3.w - m.w) * s.w)) + bt.w;
    char4 o;
    o.x = (char)((r0 > 0.f) ? 1 : ((r0 < 0.f) ? -1 : 0));
    o.y = (char)((r1 > 0.f) ? 1 : ((r1 < 0.f) ? -1 : 0));
    o.z = (char)((r2 > 0.f) ? 1 : ((r2 < 0.f) ? -1 : 0));
    o.w = (char)((r3 > 0.f) ? 1 : ((r3 < 0.f) ? -1 : 0));
    ((char4*)out)[idx] = o;
}

// BN + 2x2 maxpool + sign, int8 input (stage 2->3). 4 ch/thread.
template <int H, int C>
__global__ void bn_pool_sign4_i8_kernel(const int8_t* __restrict__ y,
                                        int8_t* __restrict__ out,
                                        const float* __restrict__ beta,
                                        int total4) {
    int idx = blockIdx.x * 256 + threadIdx.x;
    if (idx >= total4) return;
    constexpr int Ho = H / 2;
    int e = idx * 4;
    int c = e % C;
    int t = e / C;
    int ox = t % Ho; t /= Ho;
    int oy = t % Ho;
    int b  = t / Ho;
    float4 m  = *(const float4*)(g_mean + c);
    float4 s  = *(const float4*)(g_scale + c);
    float4 bt = *(const float4*)(beta + c);
    size_t base = (((size_t)b * H + 2 * oy) * H + 2 * ox) * C + c;
    char4 u0 = *(const char4*)(y + base);
    char4 u1 = *(const char4*)(y + base + C);
    char4 u2 = *(const char4*)(y + base + (size_t)H * C);
    char4 u3 = *(const char4*)(y + base + (size_t)H * C + C);
    float r0 = fmaxf(fmaxf(((float)u0.x - m.x) * s.x, ((float)u1.x - m.x) * s.x),
                     fmaxf(((float)u2.x - m.x) * s.x, ((float)u3.x - m.x) * s.x)) + bt.x;
    float r1 = fmaxf(fmaxf(((float)u0.y - m.y) * s.y, ((float)u1.y - m.y) * s.y),
                     fmaxf(((float)u2.y - m.y) * s.y, ((float)u3.y - m.y) * s.y)) + bt.y;
    float r2 = fmaxf(fmaxf(((float)u0.z - m.z) * s.z, ((float)u1.z - m.z) * s.z),
                     fmaxf(((float)u2.z - m.z) * s.z, ((float)u3.z - m.z) * s.z)) + bt.z;
    float r3 = fmaxf(fmaxf(((float)u0.w - m.w) * s.w, ((float)u1.w - m.w) * s.w),
                     fmaxf(((float)u2.w - m.w) * s.w, ((float)u3.w - m.w) * s.w)) + bt.w;
    char4 o;
    o.x = (char)((r0 > 0.f) ? 1 : ((r0 < 0.f) ? -1 : 0));
    o.y = (char)((r1 > 0.f) ? 1 : ((r1 < 0.f) ? -1 : 0));
    o.z = (char)((r2 > 0.f) ? 1 : ((r2 < 0.f) ? -1 : 0));
    o.w = (char)((r3 > 0.f) ? 1 : ((r3 < 0.f) ? -1 : 0));
    ((char4*)out)[idx] = o;
}

// ---------------------------------------------------------------------------
// Grouped 4x4 binary conv, dp2a register-windowed. Self-staged weights.
// smem tile holds int16 sign-extended activations (channel pairs -> one int).
// ---------------------------------------------------------------------------
template <int H, int C>
__global__ void conv_grp_kernel(const int8_t* __restrict__ a,
                                const float* __restrict__ w,
                                int8_t* __restrict__ out, int NS) {
    int b = blockIdx.y, oy = blockIdx.x;
    int tid = threadIdx.x;
    constexpr int PW = H + 3;
    constexpr int SPAN = (H * C) / 256;
    __shared__ __align__(16) int16_t as16[4][PW][C];
    __shared__ int8_t wgs[32 * C];
    __shared__ int2 sred[256];

    // stage + binarize weights (coalesced read w[c*32+k] -> wgs[k*C+c])
    for (int i = tid; i < 32 * C; i += 256) {
        int cc = i / 32, k = i % 32;
        float v = w[i];
        wgs[k * C + cc] = (int8_t)((v > 0.f) ? 1 : ((v < 0.f) ? -1 : 0));
    }

    // stage activations as int16 pairs
    const int8_t* abase = a + (size_t)b * H * H * C;
    int total4 = (4 * PW * C) / 4;
    for (int i = tid; i < total4; i += 256) {
        int e = i * 4;
        int cc = e % C;
        int col = (e / C) % PW;
        int r = e / (C * PW);
        int ix = col - 1, iy = oy - 1 + r;
        int v = 0;
        if (ix >= 0 && ix < H && iy >= 0 && iy < H)
            v = *(const int*)(abase + ((size_t)iy * H + ix) * C + cc);
        int b0 = (int)(char)(v);
        int b1 = (int)(char)(v >> 8);
        int b2 = (int)(char)(v >> 16);
        int b3 = (int)(char)(v >> 24);
        int2 o;
        o.x = (b0 & 0xFFFF) | (b1 << 16);
        o.y = (b2 & 0xFFFF) | (b3 << 16);
        *(int2*)(&as16[r][col][cc]) = o;
    }
    __syncthreads();

    int c = tid % C;
    int xq = tid / C;
    int g2 = c & ~1;

    int wpair[16];
#pragma unroll
    for (int k = 0; k < 16; k++) {
        int w0 = (int)wgs[k * C + c];         // l = 0 tap
        int w1 = (int)wgs[(16 + k) * C + c];  // l = 1 tap
        wpair[k] = (w0 & 0xff) | ((w1 & 0xff) << 8);
    }

    // register window: one int = 2 channels (int16 each)
    int win[4][SPAN + 3];
#pragma unroll
    for (int kh = 0; kh < 4; kh++)
#pragma unroll
        for (int t = 0; t < SPAN + 3; t++)
            win[kh][t] = *(const int*)&as16[kh][xq * SPAN + t][g2];

    int is1 = 0, is2 = 0;
#pragma unroll
    for (int j = 0; j < SPAN; j++) {
        int acc = 0;
#pragma unroll
        for (int kh = 0; kh < 4; kh++)
#pragma unroll
            for (int kw = 0; kw < 4; kw++)
                acc = dp2a_lo(win[kh][j + kw], wpair[kh * 4 + kw], acc);
        int ox = xq * SPAN + j;
        out[(((size_t)b * H + oy) * H + ox) * C + c] = (int8_t)acc;
        is1 += acc;
        is2 += acc * acc;
    }

    int slice = b * gridDim.x + blockIdx.x;
    if (C == 256) {
        g_part[(size_t)c * NS + slice]       = (float)is1;
        g_part[(size_t)(C + c) * NS + slice] = (float)is2;
    } else {
        sred[tid] = make_int2(is1, is2);
        __syncthreads();
        if (tid < C) {
            int a1 = 0, a2 = 0;
#pragma unroll
            for (int q = 0; q < 256 / C; q++) {
                a1 += sred[q * C + tid].x;
                a2 += sred[q * C + tid].y;
            }
            g_part[(size_t)tid * NS + slice]       = (float)a1;
            g_part[(size_t)(C + tid) * NS + slice] = (float)a2;
        }
    }
}

// ---------------------------------------------------------------------------
// prep: pack wp2, wp3, reorder fcw.  One kernel, block ranges.
// ---------------------------------------------------------------------------
__global__ void prep_kernel(const float* __restrict__ w2_2,
                            const float* __restrict__ w3_2,
                            const float* __restrict__ fcw,
                            int8_t* __restrict__ wp2,
                            int8_t* __restrict__ wp3,
                            float* __restrict__ fcwr) {
    int bid = blockIdx.x;
    int tid = threadIdx.x;
    if (bid < 640) {
        int i = bid * 256 + tid;  // fcwr: i = n*16384 + e, e = hw*256 + c
        int n = i / 16384;
        int e = i % 16384;
        int c = e & 255, hw = e >> 8;
        fcwr[i] = fcw[n * 16384 + c * 64 + hw];
    } else if (bid < 704) {
        int i = (bid - 640) * 256 + tid;  // wp2: 16384
        float v = w2_2[i];
        wp2[i] = (int8_t)((v > 0.f) ? 1 : ((v < 0.f) ? -1 : 0));
    } else {
        int i = (bid - 704) * 256 + tid;  // wp3: 65536
        float v = w3_2[i];
        wp3[i] = (int8_t)((v > 0.f) ? 1 : ((v < 0.f) ? -1 : 0));
    }
}

// ---------------------------------------------------------------------------
// 1x1 binary conv as dp4a GEMM with FUSED bn+sign on the input tile.
// gemm64: y2b [P,64] -> bn2_1+sign -> x wp2 [256,64] -> y3b [P,256] int8.
// ---------------------------------------------------------------------------
__global__ void gemm64_kernel(const int8_t* __restrict__ yin,
                              const int8_t* __restrict__ wp,
                              const float* __restrict__ beta,
                              int8_t* __restrict__ out) {
    const int NS = 1024;
    __shared__ __align__(16) int as[128][16];
    __shared__ float pm[64], ps[64], pb[64];
    int tid = threadIdx.x;
    if (tid < 64) {
        pm[tid] = g_mean[tid];
        ps[tid] = g_scale[tid];
        pb[tid] = beta[tid];
    }
    int c = tid;
    int wr[16];
    const int* w4 = (const int*)wp + c * 16;
#pragma unroll
    for (int k = 0; k < 16; k++) wr[k] = w4[k];
    __syncthreads();

    size_t p0 = (size_t)blockIdx.x * 128;
    const int* y4 = (const int*)(yin + p0 * 64);
    for (int i = tid; i < 2048; i += 256) {
        int c0 = (i & 15) * 4;
        int v = y4[i];
        float r0 = ((float)(char)(v)       - pm[c0])     * ps[c0]     + pb[c0];
        float r1 = ((float)(char)(v >> 8)  - pm[c0 + 1]) * ps[c0 + 1] + pb[c0 + 1];
        float r2 = ((float)(char)(v >> 16) - pm[c0 + 2]) * ps[c0 + 2] + pb[c0 + 2];
        float r3 = ((float)(char)(v >> 24) - pm[c0 + 3]) * ps[c0 + 3] + pb[c0 + 3];
        int u0 = (r0 > 0.f) ? 1 : ((r0 < 0.f) ? -1 : 0);
        int u1 = (r1 > 0.f) ? 1 : ((r1 < 0.f) ? -1 : 0);
        int u2 = (r2 > 0.f) ? 1 : ((r2 < 0.f) ? -1 : 0);
        int u3 = (r3 > 0.f) ? 1 : ((r3 < 0.f) ? -1 : 0);
        as[i >> 4][i & 15] =
            (u0 & 0xff) | ((u1 & 0xff) << 8) | ((u2 & 0xff) << 16) | (u3 << 24);
    }
    __syncthreads();

    int is1 = 0, is2 = 0;
    for (int p = 0; p < 128; p++) {
        int acc = 0;
        const int4* av = (const int4*)as[p];
#pragma unroll
        for (int k4 = 0; k4 < 4; k4++) {
            int4 v = av[k4];
            acc = __dp4a(v.x, wr[k4 * 4 + 0], acc);
            acc = __dp4a(v.y, wr[k4 * 4 + 1], acc);
            acc = __dp4a(v.z, wr[k4 * 4 + 2], acc);
            acc = __dp4a(v.w, wr[k4 * 4 + 3], acc);
        }
        out[(p0 + p) * 256 + c] = (int8_t)acc;
        is1 += acc;
        is2 += acc * acc;
    }
    g_part[(size_t)c * NS + blockIdx.x]         = (float)is1;
    g_part[(size_t)(256 + c) * NS + blockIdx.x] = (float)is2;
}

// gemm256: y4b [P,256] -> bn3_1+sign -> x wp3 [256,256] -> y5s [P,256] int16.
__global__ void gemm256_kernel(const int8_t* __restrict__ yin,
                               const int8_t* __restrict__ wp,
                               const float* __restrict__ beta,
                               int16_t* __restrict__ out) {
    const int NS = 512;
    __shared__ __align__(16) int as[64][64];
    __shared__ float pm[256], ps[256], pb[256];
    int tid = threadIdx.x;
    pm[tid] = g_mean[tid];
    ps[tid] = g_scale[tid];
    pb[tid] = beta[tid];
    int c = tid;
    int wr[64];
    const int* w4 = (const int*)wp + c * 64;
#pragma unroll
    for (int k = 0; k < 64; k++) wr[k] = w4[k];
    __syncthreads();

    size_t p0 = (size_t)blockIdx.x * 64;
    const int* y4 = (const int*)(yin + p0 * 256);
    for (int i = tid; i < 4096; i += 256) {
        int c0 = (i & 63) * 4;
        int v = y4[i];
        float r0 = ((float)(char)(v)       - pm[c0])     * ps[c0]     + pb[c0];
        float r1 = ((float)(char)(v >> 8)  - pm[c0 + 1]) * ps[c0 + 1] + pb[c0 + 1];
        float r2 = ((float)(char)(v >> 16) - pm[c0 + 2]) * ps[c0 + 2] + pb[c0 + 2];
        float r3 = ((float)(char)(v >> 24) - pm[c0 + 3]) * ps[c0 + 3] + pb[c0 + 3];
        int u0 = (r0 > 0.f) ? 1 : ((r0 < 0.f) ? -1 : 0);
        int u1 = (r1 > 0.f) ? 1 : ((r1 < 0.f) ? -1 : 0);
        int u2 = (r2 > 0.f) ? 1 : ((r2 < 0.f) ? -1 : 0);
        int u3 = (r3 > 0.f) ? 1 : ((r3 < 0.f) ? -1 : 0);
        as[i >> 6][i & 63] =
            (u0 & 0xff) | ((u1 & 0xff) << 8) | ((u2 & 0xff) << 16) | (u3 << 24);
    }
    __syncthreads();

    int is1 = 0, is2 = 0;
    for (int p = 0; p < 64; p++) {
        int acc = 0;
        const int4* av = (const int4*)as[p];
#pragma unroll
        for (int k4 = 0; k4 < 16; k4++) {
            int4 v = av[k4];
            acc = __dp4a(v.x, wr[k4 * 4 + 0], acc);
            acc = __dp4a(v.y, wr[k4 * 4 + 1], acc);
            acc = __dp4a(v.z, wr[k4 * 4 + 2], acc);
            acc = __dp4a(v.w, wr[k4 * 4 + 3], acc);
        }
        out[(p0 + p) * 256 + c] = (int16_t)acc;
        is1 += acc;
        is2 += acc * acc;
    }
    g_part[(size_t)c * NS + blockIdx.x]         = (float)is1;
    g_part[(size_t)(256 + c) * NS + blockIdx.x] = (float)is2;
}

// ---------------------------------------------------------------------------
// FC with fused bn3_2; 4 batches per block; int16 input.
// ---------------------------------------------------------------------------
#define FCB 4
__global__ void fc_kernel(const int16_t* __restrict__ y5,
                          const float* __restrict__ fcwr,
                          const float* __restrict__ fc_b,
                          const float* __restrict__ beta,
                          float* __restrict__ out) {
    int b0 = blockIdx.x * FCB;
    int tid = threadIdx.x;
    float acc[FCB][10];
#pragma unroll
    for (int bb = 0; bb < FCB; bb++)
#pragma unroll
        for (int n = 0; n < 10; n++) acc[bb][n] = 0.f;

    for (int i = tid; i < 16384; i += 256) {
        int c = i & 255;
        float m = g_mean[c], s = g_scale[c], bt = beta[c];
        float w[10];
#pragma unroll
        for (int n = 0; n < 10; n++) w[n] = fcwr[n * 16384 + i];
#pragma unroll
        for (int bb = 0; bb < FCB; bb++) {
            float v = ((float)y5[(size_t)(b0 + bb) * 16384 + i] - m) * s + bt;
#pragma unroll
            for (int n = 0; n < 10; n++) acc[bb][n] += v * w[n];
        }
    }

    __shared__ float sred[8][FCB * 10];
    int lane = tid & 31, wid = tid >> 5;
#pragma unroll
    for (int bb = 0; bb < FCB; bb++)
#pragma unroll
        for (int n = 0; n < 10; n++) {
            float v = acc[bb][n];
#pragma unroll
            for (int o = 16; o > 0; o >>= 1)
                v += __shfl_xor_sync(0xffffffffu, v, o);
            if (lane == 0) sred[wid][bb * 10 + n] = v;
        }
    __syncthreads();
    if (tid < FCB * 10) {
        float v = 0.f;
#pragma unroll
        for (int w8 = 0; w8 < 8; w8++) v += sred[w8][tid];
        int bb = tid / 10, n = tid % 10;
        out[(b0 + bb) * 10 + n] = v + fc_b[n];
    }
}

// ---------------------------------------------------------------------------
extern "C" void kernel_launch(void* const* d_in, const int* in_sizes, int n_in,
                              void* d_out, int out_size) {
    const float* x    = (const float*)d_in[0];
    const float* w1   = (const float*)d_in[1];
    const float* g1   = (const float*)d_in[2];
    const float* b1   = (const float*)d_in[3];
    const float* w2_1 = (const float*)d_in[4];
    const float* g2_1 = (const float*)d_in[5];
    const float* b2_1 = (const float*)d_in[6];
    const float* w2_2 = (const float*)d_in[7];
    const float* g2_2 = (const float*)d_in[8];
    const float* b2_2 = (const float*)d_in[9];
    const float* w3_1 = (const float*)d_in[10];
    const float* g3_1 = (const float*)d_in[11];
    const float* b3_1 = (const float*)d_in[12];
    const float* w3_2 = (const float*)d_in[13];
    const float* g3_2 = (const float*)d_in[14];
    const float* b3_2 = (const float*)d_in[15];
    const float* fcw  = (const float*)d_in[16];
    const float* fcb  = (const float*)d_in[17];
    float* out = (float*)d_out;

    float *y1, *fcwr;
    int8_t *a1, *a3, *y2b, *y3b, *y4b, *wp2, *wp3;
    int16_t *y5s;
    cudaGetSymbolAddress((void**)&y1, g_y1);
    cudaGetSymbolAddress((void**)&y2b, g_y2b);
    cudaGetSymbolAddress((void**)&y3b, g_y3b);
    cudaGetSymbolAddress((void**)&y4b, g_y4b);
    cudaGetSymbolAddress((void**)&y5s, g_y5s);
    cudaGetSymbolAddress((void**)&a1, g_a1);
    cudaGetSymbolAddress((void**)&a3, g_a3);
    cudaGetSymbolAddress((void**)&wp2, g_wp2);
    cudaGetSymbolAddress((void**)&wp3, g_wp3);
    cudaGetSymbolAddress((void**)&fcwr, g_fcwr);

    // 1-4: stage 1 + grp2 (grp2 lands in the profiled 4th slot)
    conv1_kernel<<<dim3(4, BATCH), 256>>>(x, w1, y1);
    reduce_finalize_kernel<64><<<64, 256>>>(g1, 2048, 512 * 1024);
    bn_pool_sign4_f_kernel<32, 64><<<(512 * 256 * 64 / 4 + 255) / 256, 256>>>(
        y1, a1, b1, 512 * 256 * 64 / 4);
    conv_grp_kernel<16, 64><<<dim3(16, BATCH), 256>>>(a1, w2_1, y2b, 8192);

    // 5: weight prep for gemms + fc
    prep_kernel<<<960, 256>>>(w2_2, w3_2, fcw, wp2, wp3, fcwr);

    // 6-9: stage 2
    reduce_finalize_kernel<64><<<64, 256>>>(g2_1, 8192, 512 * 256);
    gemm64_kernel<<<(512 * 256) / 128, 256>>>(y2b, wp2, b2_1, y3b);
    reduce_finalize_kernel<256><<<256, 256>>>(g2_2, 1024, 512 * 256);
    bn_pool_sign4_i8_kernel<16, 256><<<(512 * 64 * 256 / 4 + 255) / 256, 256>>>(
        y3b, a3, b2_2, 512 * 64 * 256 / 4);

    // 10-13: stage 3
    conv_grp_kernel<8, 256><<<dim3(8, BATCH), 256>>>(a3, w3_1, y4b, 4096);
    reduce_finalize_kernel<256><<<256, 256>>>(g3_1, 4096, 512 * 64);
    gemm256_kernel<<<(512 * 64) / 64, 256>>>(y4b, wp3, b3_1, y5s);
    reduce_finalize_kernel<256><<<256, 256>>>(g3_2, 512, 512 * 64);

    // 14: FC (bn3_2 fused)
    fc_kernel<<<BATCH / FCB, 256>>>(y5s, fcwr, fcb, b3_2, out);
}

// round 8
// speedup vs baseline: 1.3424x; 1.3424x over previous
#include <cuda_runtime.h>
#include <cstdint>
#include <cstdio>

// ---------------------------------------------------------------------------
// LiBNet forward, batch 512.  Round 8 = Round 7 resubmit (infra flake).
// R5 baseline (481us) + one change: conv_grp inner loop uses int16-pair LDS +
// dp4a (halves LSU+ALU issue, no register window -> no spills).
// ---------------------------------------------------------------------------

#define BATCH 512

// Scratch (device globals)
__device__ float   g_y1[512u*1024u*64u];   // conv1 out  [b,32,32,64] fp32
__device__ int8_t  g_a1[512u*256u*64u];    // sign(pool(bn1)) [b,16,16,64]
__device__ int8_t  g_y2b[512u*256u*64u];   // conv2_1 out int8
__device__ int8_t  g_a2[512u*256u*64u];    // sign(bn2_1)
__device__ int8_t  g_y3b[512u*256u*256u];  // conv2_2 out int8
__device__ int8_t  g_a3[512u*64u*256u];    // sign(pool(bn2_2)) [b,8,8,256]
__device__ int8_t  g_y4b[512u*64u*256u];   // conv3_1 out int8
__device__ int8_t  g_a4[512u*64u*256u];    // sign(bn3_1)
__device__ int16_t g_y5s[512u*64u*256u];   // conv3_2 out int16
__device__ float   g_w1s[48*64];           // sign(w1) transposed [k][c]
__device__ int8_t  g_wg2[32*64];           // sign(w2_1) transposed [k][c]
__device__ int8_t  g_wg3[32*256];          // sign(w3_1) transposed [k][c]
__device__ int8_t  g_wp2[256*64];          // sign(w2_2)
__device__ int8_t  g_wp3[256*256];         // sign(w3_2)
__device__ float   g_part[2097152];        // stats partials [c][slice]
__device__ float   g_mean[256];
__device__ float   g_scale[256];
__device__ float   g_fcwr[16384*10];       // fc_w n-major over NHWC-flatten

// ---------------------------------------------------------------------------
// weight prep
// ---------------------------------------------------------------------------
__global__ void pack_w1_kernel(const float* __restrict__ w1,
                               float* __restrict__ w1s) {
    int i = blockIdx.x * 256 + threadIdx.x;  // i = k*64 + c
    if (i >= 48 * 64) return;
    int c = i & 63, k = i >> 6;
    float v = w1[c * 48 + k];
    w1s[i] = (v > 0.f) ? 1.f : ((v < 0.f) ? -1.f : 0.f);
}

// grouped-conv weights [C,2,4,4] -> int8 transposed [k=32][c=C]
__global__ void pack_grp_kernel(const float* __restrict__ w,
                                int8_t* __restrict__ dst, int C) {
    int i = blockIdx.x * 256 + threadIdx.x;  // i = k*C + c
    if (i >= 32 * C) return;
    int c = i % C, k = i / C;
    float v = w[c * 32 + k];
    dst[i] = (int8_t)((v > 0.f) ? 1 : ((v < 0.f) ? -1 : 0));
}

__global__ void pack_sign_kernel(const float* __restrict__ w,
                                 int8_t* __restrict__ dst, int n) {
    int i = blockIdx.x * 256 + threadIdx.x;
    if (i >= n) return;
    float v = w[i];
    dst[i] = (int8_t)((v > 0.f) ? 1 : ((v < 0.f) ? -1 : 0));
}

__global__ void fcw_reorder_kernel(const float* __restrict__ fcw,
                                   float* __restrict__ fcwr) {
    int i = blockIdx.x * 256 + threadIdx.x;  // i = n*16384 + e, e = hw*256 + c
    if (i >= 16384 * 10) return;
    int n = i / 16384;
    int e = i % 16384;
    int c = e & 255, hw = e >> 8;
    fcwr[i] = fcw[n * 16384 + c * 64 + hw];
}

// ---------------------------------------------------------------------------
// conv1: x [b,3,32,32] NCHW, pad (t1,b2,l1,r2), out NHWC [b,32,32,64] fp32.
// 4 output rows per block; fused channel stats -> g_part [c][slice].
// ---------------------------------------------------------------------------
__global__ void conv1_kernel(const float* __restrict__ x,
                             const float* __restrict__ w1s,
                             float* __restrict__ y1) {
    const int NS = 4096;  // 8 * 512 slices
    int b = blockIdx.y, oy0 = blockIdx.x * 4;
    int tid = threadIdx.x;
    int c = tid & 63, xq = tid >> 6;

    __shared__ float xs[3][7][36];
    __shared__ float2 sred[256];

    for (int i = tid; i < 3 * 7 * 36; i += 256) {
        int col = i % 36;
        int r   = (i / 36) % 7;
        int ci  = i / 252;
        int ix = col - 1, iy = oy0 - 1 + r;
        float v = 0.f;
        if (ix >= 0 && ix < 32 && iy >= 0 && iy < 32)
            v = x[(((size_t)b * 3 + ci) * 32 + iy) * 32 + ix];
        xs[ci][r][col] = v;
    }

    float wr[48];
#pragma unroll
    for (int k = 0; k < 48; k++) wr[k] = w1s[k * 64 + c];
    __syncthreads();

    float s1 = 0.f, s2 = 0.f;
#pragma unroll
    for (int r = 0; r < 4; r++) {
        float acc[8];
#pragma unroll
        for (int j = 0; j < 8; j++) acc[j] = 0.f;
#pragma unroll
        for (int ci = 0; ci < 3; ci++) {
#pragma unroll
            for (int kh = 0; kh < 4; kh++) {
                float rx[11];
#pragma unroll
                for (int t = 0; t < 11; t++) rx[t] = xs[ci][r + kh][xq * 8 + t];
#pragma unroll
                for (int kw = 0; kw < 4; kw++) {
                    float wv = wr[ci * 16 + kh * 4 + kw];
#pragma unroll
                    for (int j = 0; j < 8; j++) acc[j] += wv * rx[j + kw];
                }
            }
        }
        size_t obase = (((size_t)b * 32 + oy0 + r) * 32 + xq * 8) * 64 + c;
#pragma unroll
        for (int j = 0; j < 8; j++) {
            y1[obase + (size_t)j * 64] = acc[j];
            s1 += acc[j];
            s2 += acc[j] * acc[j];
        }
    }

    sred[tid] = make_float2(s1, s2);
    __syncthreads();
    if (tid < 64) {
        float2 a = sred[tid], b1 = sred[tid + 64], c1 = sred[tid + 128],
               d1 = sred[tid + 192];
        int slice = b * 8 + blockIdx.x;
        g_part[tid * NS + slice]        = a.x + b1.x + c1.x + d1.x;
        g_part[(64 + tid) * NS + slice] = a.y + b1.y + c1.y + d1.y;
    }
}

// ---------------------------------------------------------------------------
// Reduce partials (coalesced: [c][slice]) + shift-BN finalize.
// ---------------------------------------------------------------------------
template <int C>
__global__ void reduce_finalize_kernel(const float* __restrict__ gamma,
                                       int nslices, int P) {
    int c = blockIdx.x;
    int tid = threadIdx.x;
    float s1 = 0.f, s2 = 0.f;
    const float* p1 = g_part + (size_t)c * nslices;
    const float* p2 = g_part + (size_t)(C + c) * nslices;
#pragma unroll 4
    for (int s = tid; s < nslices; s += 256) {
        s1 += p1[s];
        s2 += p2[s];
    }
    __shared__ double sd1[256], sd2[256];
    sd1[tid] = (double)s1;
    sd2[tid] = (double)s2;
    __syncthreads();
    for (int s = 128; s > 0; s >>= 1) {
        if (tid < s) {
            sd1[tid] += sd1[tid + s];
            sd2[tid] += sd2[tid + s];
        }
        __syncthreads();
    }
    if (tid == 0) {
        double mean = sd1[0] / (double)P;
        double var  = sd2[0] / (double)P - mean * mean;
        double inv  = (double)gamma[c] / sqrt(var + 1e-5);
        double sh   = rint(log2(fabs(inv) + 1e-12));
        if (sh > 4.0) sh = 4.0;
        if (sh < -4.0) sh = -4.0;
        double sgn = (inv > 0.0) ? 1.0 : ((inv < 0.0) ? -1.0 : 0.0);
        g_mean[c]  = (float)mean;
        g_scale[c] = (float)(sgn * exp2(sh));
    }
}

// ---------------------------------------------------------------------------
// BN + 2x2 maxpool + sign, fp32 input (stage 1). 4 ch/thread.
// ---------------------------------------------------------------------------
template <int H, int C>
__global__ void bn_pool_sign4_f_kernel(const float* __restrict__ y,
                                       int8_t* __restrict__ out,
                                       const float* __restrict__ beta,
                                       int total4) {
    int idx = blockIdx.x * 256 + threadIdx.x;
    if (idx >= total4) return;
    constexpr int Ho = H / 2;
    int e = idx * 4;
    int c = e % C;
    int t = e / C;
    int ox = t % Ho; t /= Ho;
    int oy = t % Ho;
    int b  = t / Ho;
    float4 m  = *(const float4*)(g_mean + c);
    float4 s  = *(const float4*)(g_scale + c);
    float4 bt = *(const float4*)(beta + c);
    size_t base = (((size_t)b * H + 2 * oy) * H + 2 * ox) * C + c;
    float4 v0 = *(const float4*)(y + base);
    float4 v1 = *(const float4*)(y + base + C);
    float4 v2 = *(const float4*)(y + base + (size_t)H * C);
    float4 v3 = *(const float4*)(y + base + (size_t)H * C + C);
    float r0 = fmaxf(fmaxf((v0.x - m.x) * s.x, (v1.x - m.x) * s.x),
                     fmaxf((v2.x - m.x) * s.x, (v3.x - m.x) * s.x)) + bt.x;
    float r1 = fmaxf(fmaxf((v0.y - m.y) * s.y, (v1.y - m.y) * s.y),
                     fmaxf((v2.y - m.y) * s.y, (v3.y - m.y) * s.y)) + bt.y;
    float r2 = fmaxf(fmaxf((v0.z - m.z) * s.z, (v1.z - m.z) * s.z),
                     fmaxf((v2.z - m.z) * s.z, (v3.z - m.z) * s.z)) + bt.z;
    float r3 = fmaxf(fmaxf((v0.w - m.w) * s.w, (v1.w - m.w) * s.w),
                     fmaxf((v2.w - m.w) * s.w, (v3.w - m.w) * s.w)) + bt.w;
    char4 o;
    o.x = (char)((r0 > 0.f) ? 1 : ((r0 < 0.f) ? -1 : 0));
    o.y = (char)((r1 > 0.f) ? 1 : ((r1 < 0.f) ? -1 : 0));
    o.z = (char)((r2 > 0.f) ? 1 : ((r2 < 0.f) ? -1 : 0));
    o.w = (char)((r3 > 0.f) ? 1 : ((r3 < 0.f) ? -1 : 0));
    ((char4*)out)[idx] = o;
}

// BN + 2x2 maxpool + sign, int8 input (stage 2->3). 4 ch/thread.
template <int H, int C>
__global__ void bn_pool_sign4_i8_kernel(const int8_t* __restrict__ y,
                                        int8_t* __restrict__ out,
                                        const float* __restrict__ beta,
                                        int total4) {
    int idx = blockIdx.x * 256 + threadIdx.x;
    if (idx >= total4) return;
    constexpr int Ho = H / 2;
    int e = idx * 4;
    int c = e % C;
    int t = e / C;
    int ox = t % Ho; t /= Ho;
    int oy = t % Ho;
    int b  = t / Ho;
    float4 m  = *(const float4*)(g_mean + c);
    float4 s  = *(const float4*)(g_scale + c);
    float4 bt = *(const float4*)(beta + c);
    size_t base = (((size_t)b * H + 2 * oy) * H + 2 * ox) * C + c;
    char4 u0 = *(const char4*)(y + base);
    char4 u1 = *(const char4*)(y + base + C);
    char4 u2 = *(const char4*)(y + base + (size_t)H * C);
    char4 u3 = *(const char4*)(y + base + (size_t)H * C + C);
    float r0 = fmaxf(fmaxf(((float)u0.x - m.x) * s.x, ((float)u1.x - m.x) * s.x),
                     fmaxf(((float)u2.x - m.x) * s.x, ((float)u3.x - m.x) * s.x)) + bt.x;
    float r1 = fmaxf(fmaxf(((float)u0.y - m.y) * s.y, ((float)u1.y - m.y) * s.y),
                     fmaxf(((float)u2.y - m.y) * s.y, ((float)u3.y - m.y) * s.y)) + bt.y;
    float r2 = fmaxf(fmaxf(((float)u0.z - m.z) * s.z, ((float)u1.z - m.z) * s.z),
                     fmaxf(((float)u2.z - m.z) * s.z, ((float)u3.z - m.z) * s.z)) + bt.z;
    float r3 = fmaxf(fmaxf(((float)u0.w - m.w) * s.w, ((float)u1.w - m.w) * s.w),
                     fmaxf(((float)u2.w - m.w) * s.w, ((float)u3.w - m.w) * s.w)) + bt.w;
    char4 o;
    o.x = (char)((r0 > 0.f) ? 1 : ((r0 < 0.f) ? -1 : 0));
    o.y = (char)((r1 > 0.f) ? 1 : ((r1 < 0.f) ? -1 : 0));
    o.z = (char)((r2 > 0.f) ? 1 : ((r2 < 0.f) ? -1 : 0));
    o.w = (char)((r3 > 0.f) ? 1 : ((r3 < 0.f) ? -1 : 0));
    ((char4*)out)[idx] = o;
}

// BN + sign, int8 input, elementwise. 4 ch/thread.
template <int C>
__global__ void bn_sign4_i8_kernel(const int8_t* __restrict__ y,
                                   int8_t* __restrict__ out,
                                   const float* __restrict__ beta,
                                   int total4) {
    int idx = blockIdx.x * 256 + threadIdx.x;
    if (idx >= total4) return;
    int c = (idx * 4) % C;
    float4 m  = *(const float4*)(g_mean + c);
    float4 s  = *(const float4*)(g_scale + c);
    float4 bt = *(const float4*)(beta + c);
    char4 u = ((const char4*)y)[idx];
    float r0 = ((float)u.x - m.x) * s.x + bt.x;
    float r1 = ((float)u.y - m.y) * s.y + bt.y;
    float r2 = ((float)u.z - m.z) * s.z + bt.z;
    float r3 = ((float)u.w - m.w) * s.w + bt.w;
    char4 o;
    o.x = (char)((r0 > 0.f) ? 1 : ((r0 < 0.f) ? -1 : 0));
    o.y = (char)((r1 > 0.f) ? 1 : ((r1 < 0.f) ? -1 : 0));
    o.z = (char)((r2 > 0.f) ? 1 : ((r2 < 0.f) ? -1 : 0));
    o.w = (char)((r3 > 0.f) ? 1 : ((r3 < 0.f) ? -1 : 0));
    ((char4*)out)[idx] = o;
}

// ---------------------------------------------------------------------------
// Grouped 4x4 binary conv. int8 smem tile (as in R5), but the inner loop does
// ONE LDS.16 (channel pair g2,g2+1 are adjacent bytes) + ONE dp4a per tap pair
// with packed weights (upper 2 bytes zero -> contribute 0). No reg window.
// ---------------------------------------------------------------------------
template <int H, int C>
__global__ void conv_grp_kernel(const int8_t* __restrict__ a,
                                const int8_t* __restrict__ wg,
                                int8_t* __restrict__ out, int NS) {
    int b = blockIdx.y, oy = blockIdx.x;
    int tid = threadIdx.x;
    constexpr int PW = H + 3;
    __shared__ __align__(16) int8_t as[4][PW][C];
    __shared__ int2 sred[256];

    const int8_t* abase = a + (size_t)b * H * H * C;
    int total4 = (4 * PW * C) / 4;
    for (int i = tid; i < total4; i += 256) {
        int e = i * 4;
        int cc = e % C;
        int col = (e / C) % PW;
        int r = e / (C * PW);
        int ix = col - 1, iy = oy - 1 + r;
        int v = 0;
        if (ix >= 0 && ix < H && iy >= 0 && iy < H)
            v = *(const int*)(abase + ((size_t)iy * H + ix) * C + cc);
        *(int*)(&as[r][col][cc]) = v;
    }

    int c = tid % C;
    int xq = tid / C;
    int g2 = c & ~1;
    // packed weight pairs: byte0 = l=0 tap, byte1 = l=1 tap (coalesced loads)
    int wpair[16];
#pragma unroll
    for (int k = 0; k < 16; k++) {
        int w0 = (int)wg[k * C + c];
        int w1 = (int)wg[(16 + k) * C + c];
        wpair[k] = (w0 & 0xff) | ((w1 & 0xff) << 8);
    }
    __syncthreads();

    int is1 = 0, is2 = 0;
    constexpr int SPAN = (H * C) / 256;
    for (int j = 0; j < SPAN; j++) {
        int ox = xq * SPAN + j;
        int acc = 0;
#pragma unroll
        for (int kh = 0; kh < 4; kh++) {
#pragma unroll
            for (int kw = 0; kw < 4; kw++) {
                int v = (int)*(const uint16_t*)&as[kh][ox + kw][g2];
                acc = __dp4a(v, wpair[kh * 4 + kw], acc);
            }
        }
        out[(((size_t)b * H + oy) * H + ox) * C + c] = (int8_t)acc;
        is1 += acc;
        is2 += acc * acc;
    }

    int slice = b * gridDim.x + blockIdx.x;
    if (C == 256) {
        g_part[(size_t)c * NS + slice]       = (float)is1;
        g_part[(size_t)(C + c) * NS + slice] = (float)is2;
    } else {
        sred[tid] = make_int2(is1, is2);
        __syncthreads();
        if (tid < C) {
            int a1 = 0, a2 = 0;
#pragma unroll
            for (int q = 0; q < 256 / C; q++) {
                a1 += sred[q * C + tid].x;
                a2 += sred[q * C + tid].y;
            }
            g_part[(size_t)tid * NS + slice]       = (float)a1;
            g_part[(size_t)(C + tid) * NS + slice] = (float)a2;
        }
    }
}

// ---------------------------------------------------------------------------
// 1x1 binary conv as dp4a GEMM, int8/int16 out, int stats.
// ---------------------------------------------------------------------------
__global__ void gemm64_kernel(const int8_t* __restrict__ a,
                              const int8_t* __restrict__ wp,
                              int8_t* __restrict__ out) {
    const int NS = 1024;
    __shared__ __align__(16) int as[128][16];
    int c = threadIdx.x;
    int wr[16];
    const int* w4 = (const int*)wp + c * 16;
#pragma unroll
    for (int k = 0; k < 16; k++) wr[k] = w4[k];
    size_t p0 = (size_t)blockIdx.x * 128;
    const int* a4 = (const int*)(a + p0 * 64);
    for (int i = threadIdx.x; i < 2048; i += 256) as[i >> 4][i & 15] = a4[i];
    __syncthreads();
    int is1 = 0, is2 = 0;
    for (int p = 0; p < 128; p++) {
        int acc = 0;
        const int4* av = (const int4*)as[p];
#pragma unroll
        for (int k4 = 0; k4 < 4; k4++) {
            int4 v = av[k4];
            acc = __dp4a(v.x, wr[k4 * 4 + 0], acc);
            acc = __dp4a(v.y, wr[k4 * 4 + 1], acc);
            acc = __dp4a(v.z, wr[k4 * 4 + 2], acc);
            acc = __dp4a(v.w, wr[k4 * 4 + 3], acc);
        }
        out[(p0 + p) * 256 + c] = (int8_t)acc;
        is1 += acc;
        is2 += acc * acc;
    }
    g_part[(size_t)c * NS + blockIdx.x]         = (float)is1;
    g_part[(size_t)(256 + c) * NS + blockIdx.x] = (float)is2;
}

__global__ void gemm256_kernel(const int8_t* __restrict__ a,
                               const int8_t* __restrict__ wp,
                               int16_t* __restrict__ out) {
    const int NS = 512;
    __shared__ __align__(16) int as[64][64];
    int c = threadIdx.x;
    int wr[64];
    const int* w4 = (const int*)wp + c * 64;
#pragma unroll
    for (int k = 0; k < 64; k++) wr[k] = w4[k];
    size_t p0 = (size_t)blockIdx.x * 64;
    const int* a4 = (const int*)(a + p0 * 256);
    for (int i = threadIdx.x; i < 4096; i += 256) as[i >> 6][i & 63] = a4[i];
    __syncthreads();
    int is1 = 0, is2 = 0;
    for (int p = 0; p < 64; p++) {
        int acc = 0;
        const int4* av = (const int4*)as[p];
#pragma unroll
        for (int k4 = 0; k4 < 16; k4++) {
            int4 v = av[k4];
            acc = __dp4a(v.x, wr[k4 * 4 + 0], acc);
            acc = __dp4a(v.y, wr[k4 * 4 + 1], acc);
            acc = __dp4a(v.z, wr[k4 * 4 + 2], acc);
            acc = __dp4a(v.w, wr[k4 * 4 + 3], acc);
        }
        out[(p0 + p) * 256 + c] = (int16_t)acc;
        is1 += acc;
        is2 += acc * acc;
    }
    g_part[(size_t)c * NS + blockIdx.x]         = (float)is1;
    g_part[(size_t)(256 + c) * NS + blockIdx.x] = (float)is2;
}

// ---------------------------------------------------------------------------
// FC with fused bn3_2; 4 batches per block; int16 input.
// ---------------------------------------------------------------------------
#define FCB 4
__global__ void fc_kernel(const int16_t* __restrict__ y5,
                          const float* __restrict__ fcwr,
                          const float* __restrict__ fc_b,
                          const float* __restrict__ beta,
                          float* __restrict__ out) {
    int b0 = blockIdx.x * FCB;
    int tid = threadIdx.x;
    float acc[FCB][10];
#pragma unroll
    for (int bb = 0; bb < FCB; bb++)
#pragma unroll
        for (int n = 0; n < 10; n++) acc[bb][n] = 0.f;

    for (int i = tid; i < 16384; i += 256) {
        int c = i & 255;
        float m = g_mean[c], s = g_scale[c], bt = beta[c];
        float w[10];
#pragma unroll
        for (int n = 0; n < 10; n++) w[n] = fcwr[n * 16384 + i];
#pragma unroll
        for (int bb = 0; bb < FCB; bb++) {
            float v = ((float)y5[(size_t)(b0 + bb) * 16384 + i] - m) * s + bt;
#pragma unroll
            for (int n = 0; n < 10; n++) acc[bb][n] += v * w[n];
        }
    }

    __shared__ float sred[8][FCB * 10];
    int lane = tid & 31, wid = tid >> 5;
#pragma unroll
    for (int bb = 0; bb < FCB; bb++)
#pragma unroll
        for (int n = 0; n < 10; n++) {
            float v = acc[bb][n];
#pragma unroll
            for (int o = 16; o > 0; o >>= 1)
                v += __shfl_xor_sync(0xffffffffu, v, o);
            if (lane == 0) sred[wid][bb * 10 + n] = v;
        }
    __syncthreads();
    if (tid < FCB * 10) {
        float v = 0.f;
#pragma unroll
        for (int w8 = 0; w8 < 8; w8++) v += sred[w8][tid];
        int bb = tid / 10, n = tid % 10;
        out[(b0 + bb) * 10 + n] = v + fc_b[n];
    }
}

// ---------------------------------------------------------------------------
extern "C" void kernel_launch(void* const* d_in, const int* in_sizes, int n_in,
                              void* d_out, int out_size) {
    const float* x    = (const float*)d_in[0];
    const float* w1   = (const float*)d_in[1];
    const float* g1   = (const float*)d_in[2];
    const float* b1   = (const float*)d_in[3];
    const float* w2_1 = (const float*)d_in[4];
    const float* g2_1 = (const float*)d_in[5];
    const float* b2_1 = (const float*)d_in[6];
    const float* w2_2 = (const float*)d_in[7];
    const float* g2_2 = (const float*)d_in[8];
    const float* b2_2 = (const float*)d_in[9];
    const float* w3_1 = (const float*)d_in[10];
    const float* g3_1 = (const float*)d_in[11];
    const float* b3_1 = (const float*)d_in[12];
    const float* w3_2 = (const float*)d_in[13];
    const float* g3_2 = (const float*)d_in[14];
    const float* b3_2 = (const float*)d_in[15];
    const float* fcw  = (const float*)d_in[16];
    const float* fcb  = (const float*)d_in[17];
    float* out = (float*)d_out;

    float *y1, *fcwr, *w1s;
    int8_t *a1, *a2, *a3, *a4, *y2b, *y3b, *y4b, *wp2, *wp3, *wg2, *wg3;
    int16_t *y5s;
    cudaGetSymbolAddress((void**)&y1, g_y1);
    cudaGetSymbolAddress((void**)&y2b, g_y2b);
    cudaGetSymbolAddress((void**)&y3b, g_y3b);
    cudaGetSymbolAddress((void**)&y4b, g_y4b);
    cudaGetSymbolAddress((void**)&y5s, g_y5s);
    cudaGetSymbolAddress((void**)&a1, g_a1);
    cudaGetSymbolAddress((void**)&a2, g_a2);
    cudaGetSymbolAddress((void**)&a3, g_a3);
    cudaGetSymbolAddress((void**)&a4, g_a4);
    cudaGetSymbolAddress((void**)&wp2, g_wp2);
    cudaGetSymbolAddress((void**)&wp3, g_wp3);
    cudaGetSymbolAddress((void**)&wg2, g_wg2);
    cudaGetSymbolAddress((void**)&wg3, g_wg3);
    cudaGetSymbolAddress((void**)&fcwr, g_fcwr);
    cudaGetSymbolAddress((void**)&w1s, g_w1s);

    // Stage 1
    pack_w1_kernel<<<12, 256>>>(w1, w1s);
    conv1_kernel<<<dim3(8, BATCH), 256>>>(x, w1s, y1);
    reduce_finalize_kernel<64><<<64, 256>>>(g1, 4096, 512 * 1024);
    bn_pool_sign4_f_kernel<32, 64><<<(512 * 256 * 64 / 4 + 255) / 256, 256>>>(
        y1, a1, b1, 512 * 256 * 64 / 4);

    // weight prep for later stages
    pack_grp_kernel<<<8, 256>>>(w2_1, wg2, 64);
    pack_grp_kernel<<<32, 256>>>(w3_1, wg3, 256);
    pack_sign_kernel<<<64, 256>>>(w2_2, wp2, 256 * 64);
    pack_sign_kernel<<<256, 256>>>(w3_2, wp3, 256 * 256);
    fcw_reorder_kernel<<<640, 256>>>(fcw, fcwr);

    // Stage 2
    conv_grp_kernel<16, 64><<<dim3(16, BATCH), 256>>>(a1, wg2, y2b, 8192);
    reduce_finalize_kernel<64><<<64, 256>>>(g2_1, 8192, 512 * 256);
    bn_sign4_i8_kernel<64><<<(512 * 256 * 64 / 4 + 255) / 256, 256>>>(
        y2b, a2, b2_1, 512 * 256 * 64 / 4);

    gemm64_kernel<<<(512 * 256) / 128, 256>>>(a2, wp2, y3b);
    reduce_finalize_kernel<256><<<256, 256>>>(g2_2, 1024, 512 * 256);
    bn_pool_sign4_i8_kernel<16, 256><<<(512 * 64 * 256 / 4 + 255) / 256, 256>>>(
        y3b, a3, b2_2, 512 * 64 * 256 / 4);

    // Stage 3
    conv_grp_kernel<8, 256><<<dim3(8, BATCH), 256>>>(a3, wg3, y4b, 4096);
    reduce_finalize_kernel<256><<<256, 256>>>(g3_1, 4096, 512 * 64);
    bn_sign4_i8_kernel<256><<<(512 * 64 * 256 / 4 + 255) / 256, 256>>>(
        y4b, a4, b3_1, 512 * 64 * 256 / 4);

    gemm256_kernel<<<(512 * 64) / 64, 256>>>(a4, wp3, y5s);
    reduce_finalize_kernel<256><<<256, 256>>>(g3_2, 512, 512 * 64);

    // FC (bn3_2 fused)
    fc_kernel<<<BATCH / FCB, 256>>>(y5s, fcwr, fcb, b3_2, out);
}

// round 9
// speedup vs baseline: 1.4080x; 1.0489x over previous
#include <cuda_runtime.h>
#include <cstdint>
#include <cstdio>

// ---------------------------------------------------------------------------
// LiBNet forward, batch 512.  Round 9 = R8 (448us) + re-land two independent
// R6 components never implicated in its regression:
//   (1) BN+sign fused into gemm64/gemm256 tile loaders (drops 2 bn_sign
//       kernels + a2/a4 round trips)
//   (2) all weight prep merged into one block-ranged kernel (19->14 launches)
// ---------------------------------------------------------------------------

#define BATCH 512

// Scratch (device globals)
__device__ float   g_y1[512u*1024u*64u];   // conv1 out  [b,32,32,64] fp32
__device__ int8_t  g_a1[512u*256u*64u];    // sign(pool(bn1)) [b,16,16,64]
__device__ int8_t  g_y2b[512u*256u*64u];   // conv2_1 out int8
__device__ int8_t  g_y3b[512u*256u*256u];  // conv2_2 out int8
__device__ int8_t  g_a3[512u*64u*256u];    // sign(pool(bn2_2)) [b,8,8,256]
__device__ int8_t  g_y4b[512u*64u*256u];   // conv3_1 out int8
__device__ int16_t g_y5s[512u*64u*256u];   // conv3_2 out int16
__device__ float   g_w1s[48*64];           // sign(w1) transposed [k][c]
__device__ int8_t  g_wg2[32*64];           // sign(w2_1) transposed [k][c]
__device__ int8_t  g_wg3[32*256];          // sign(w3_1) transposed [k][c]
__device__ int8_t  g_wp2[256*64];          // sign(w2_2)
__device__ int8_t  g_wp3[256*256];         // sign(w3_2)
__device__ float   g_part[2097152];        // stats partials [c][slice]
__device__ float   g_mean[256];
__device__ float   g_scale[256];
__device__ float   g_fcwr[16384*10];       // fc_w n-major over NHWC-flatten

// ---------------------------------------------------------------------------
// prep: all weight packing in one kernel (block ranges; each range exact).
//  [0,640)    fcwr reorder      163840 elems
//  [640,896)  wp3 sign          65536
//  [896,960)  wp2 sign          16384
//  [960,992)  wg3 transposed     8192
//  [992,1000) wg2 transposed     2048
//  [1000,1012) w1s transposed    3072
// ---------------------------------------------------------------------------
__global__ void prep_kernel(const float* __restrict__ w1,
                            const float* __restrict__ w2_1,
                            const float* __restrict__ w3_1,
                            const float* __restrict__ w2_2,
                            const float* __restrict__ w3_2,
                            const float* __restrict__ fcw,
                            float* __restrict__ w1s,
                            int8_t* __restrict__ wg2,
                            int8_t* __restrict__ wg3,
                            int8_t* __restrict__ wp2,
                            int8_t* __restrict__ wp3,
                            float* __restrict__ fcwr) {
    int bid = blockIdx.x, tid = threadIdx.x;
    if (bid < 640) {
        int i = bid * 256 + tid;  // i = n*16384 + e, e = hw*256 + c
        int n = i / 16384;
        int e = i % 16384;
        int c = e & 255, hw = e >> 8;
        fcwr[i] = fcw[n * 16384 + c * 64 + hw];
    } else if (bid < 896) {
        int i = (bid - 640) * 256 + tid;
        float v = w3_2[i];
        wp3[i] = (int8_t)((v > 0.f) ? 1 : ((v < 0.f) ? -1 : 0));
    } else if (bid < 960) {
        int i = (bid - 896) * 256 + tid;
        float v = w2_2[i];
        wp2[i] = (int8_t)((v > 0.f) ? 1 : ((v < 0.f) ? -1 : 0));
    } else if (bid < 992) {
        int i = (bid - 960) * 256 + tid;  // i = k*256 + c
        int c = i & 255, k = i >> 8;
        float v = w3_1[c * 32 + k];
        wg3[i] = (int8_t)((v > 0.f) ? 1 : ((v < 0.f) ? -1 : 0));
    } else if (bid < 1000) {
        int i = (bid - 992) * 256 + tid;  // i = k*64 + c
        int c = i & 63, k = i >> 6;
        float v = w2_1[c * 32 + k];
        wg2[i] = (int8_t)((v > 0.f) ? 1 : ((v < 0.f) ? -1 : 0));
    } else {
        int i = (bid - 1000) * 256 + tid;  // i = k*64 + c
        int c = i & 63, k = i >> 6;
        float v = w1[c * 48 + k];
        w1s[i] = (v > 0.f) ? 1.f : ((v < 0.f) ? -1.f : 0.f);
    }
}

// ---------------------------------------------------------------------------
// conv1: x [b,3,32,32] NCHW, pad (t1,b2,l1,r2), out NHWC [b,32,32,64] fp32.
// 4 output rows per block; fused channel stats -> g_part [c][slice].
// ---------------------------------------------------------------------------
__global__ void conv1_kernel(const float* __restrict__ x,
                             const float* __restrict__ w1s,
                             float* __restrict__ y1) {
    const int NS = 4096;  // 8 * 512 slices
    int b = blockIdx.y, oy0 = blockIdx.x * 4;
    int tid = threadIdx.x;
    int c = tid & 63, xq = tid >> 6;

    __shared__ float xs[3][7][36];
    __shared__ float2 sred[256];

    for (int i = tid; i < 3 * 7 * 36; i += 256) {
        int col = i % 36;
        int r   = (i / 36) % 7;
        int ci  = i / 252;
        int ix = col - 1, iy = oy0 - 1 + r;
        float v = 0.f;
        if (ix >= 0 && ix < 32 && iy >= 0 && iy < 32)
            v = x[(((size_t)b * 3 + ci) * 32 + iy) * 32 + ix];
        xs[ci][r][col] = v;
    }

    float wr[48];
#pragma unroll
    for (int k = 0; k < 48; k++) wr[k] = w1s[k * 64 + c];
    __syncthreads();

    float s1 = 0.f, s2 = 0.f;
#pragma unroll
    for (int r = 0; r < 4; r++) {
        float acc[8];
#pragma unroll
        for (int j = 0; j < 8; j++) acc[j] = 0.f;
#pragma unroll
        for (int ci = 0; ci < 3; ci++) {
#pragma unroll
            for (int kh = 0; kh < 4; kh++) {
                float rx[11];
#pragma unroll
                for (int t = 0; t < 11; t++) rx[t] = xs[ci][r + kh][xq * 8 + t];
#pragma unroll
                for (int kw = 0; kw < 4; kw++) {
                    float wv = wr[ci * 16 + kh * 4 + kw];
#pragma unroll
                    for (int j = 0; j < 8; j++) acc[j] += wv * rx[j + kw];
                }
            }
        }
        size_t obase = (((size_t)b * 32 + oy0 + r) * 32 + xq * 8) * 64 + c;
#pragma unroll
        for (int j = 0; j < 8; j++) {
            y1[obase + (size_t)j * 64] = acc[j];
            s1 += acc[j];
            s2 += acc[j] * acc[j];
        }
    }

    sred[tid] = make_float2(s1, s2);
    __syncthreads();
    if (tid < 64) {
        float2 a = sred[tid], b1 = sred[tid + 64], c1 = sred[tid + 128],
               d1 = sred[tid + 192];
        int slice = b * 8 + blockIdx.x;
        g_part[tid * NS + slice]        = a.x + b1.x + c1.x + d1.x;
        g_part[(64 + tid) * NS + slice] = a.y + b1.y + c1.y + d1.y;
    }
}

// ---------------------------------------------------------------------------
// Reduce partials (coalesced: [c][slice]) + shift-BN finalize.
// ---------------------------------------------------------------------------
template <int C>
__global__ void reduce_finalize_kernel(const float* __restrict__ gamma,
                                       int nslices, int P) {
    int c = blockIdx.x;
    int tid = threadIdx.x;
    float s1 = 0.f, s2 = 0.f;
    const float* p1 = g_part + (size_t)c * nslices;
    const float* p2 = g_part + (size_t)(C + c) * nslices;
#pragma unroll 4
    for (int s = tid; s < nslices; s += 256) {
        s1 += p1[s];
        s2 += p2[s];
    }
    __shared__ double sd1[256], sd2[256];
    sd1[tid] = (double)s1;
    sd2[tid] = (double)s2;
    __syncthreads();
    for (int s = 128; s > 0; s >>= 1) {
        if (tid < s) {
            sd1[tid] += sd1[tid + s];
            sd2[tid] += sd2[tid + s];
        }
        __syncthreads();
    }
    if (tid == 0) {
        double mean = sd1[0] / (double)P;
        double var  = sd2[0] / (double)P - mean * mean;
        double inv  = (double)gamma[c] / sqrt(var + 1e-5);
        double sh   = rint(log2(fabs(inv) + 1e-12));
        if (sh > 4.0) sh = 4.0;
        if (sh < -4.0) sh = -4.0;
        double sgn = (inv > 0.0) ? 1.0 : ((inv < 0.0) ? -1.0 : 0.0);
        g_mean[c]  = (float)mean;
        g_scale[c] = (float)(sgn * exp2(sh));
    }
}

// ---------------------------------------------------------------------------
// BN + 2x2 maxpool + sign, fp32 input (stage 1). 4 ch/thread.
// ---------------------------------------------------------------------------
template <int H, int C>
__global__ void bn_pool_sign4_f_kernel(const float* __restrict__ y,
                                       int8_t* __restrict__ out,
                                       const float* __restrict__ beta,
                                       int total4) {
    int idx = blockIdx.x * 256 + threadIdx.x;
    if (idx >= total4) return;
    constexpr int Ho = H / 2;
    int e = idx * 4;
    int c = e % C;
    int t = e / C;
    int ox = t % Ho; t /= Ho;
    int oy = t % Ho;
    int b  = t / Ho;
    float4 m  = *(const float4*)(g_mean + c);
    float4 s  = *(const float4*)(g_scale + c);
    float4 bt = *(const float4*)(beta + c);
    size_t base = (((size_t)b * H + 2 * oy) * H + 2 * ox) * C + c;
    float4 v0 = *(const float4*)(y + base);
    float4 v1 = *(const float4*)(y + base + C);
    float4 v2 = *(const float4*)(y + base + (size_t)H * C);
    float4 v3 = *(const float4*)(y + base + (size_t)H * C + C);
    float r0 = fmaxf(fmaxf((v0.x - m.x) * s.x, (v1.x - m.x) * s.x),
                     fmaxf((v2.x - m.x) * s.x, (v3.x - m.x) * s.x)) + bt.x;
    float r1 = fmaxf(fmaxf((v0.y - m.y) * s.y, (v1.y - m.y) * s.y),
                     fmaxf((v2.y - m.y) * s.y, (v3.y - m.y) * s.y)) + bt.y;
    float r2 = fmaxf(fmaxf((v0.z - m.z) * s.z, (v1.z - m.z) * s.z),
                     fmaxf((v2.z - m.z) * s.z, (v3.z - m.z) * s.z)) + bt.z;
    float r3 = fmaxf(fmaxf((v0.w - m.w) * s.w, (v1.w - m.w) * s.w),
                     fmaxf((v2.w - m.w) * s.w, (v3.w - m.w) * s.w)) + bt.w;
    char4 o;
    o.x = (char)((r0 > 0.f) ? 1 : ((r0 < 0.f) ? -1 : 0));
    o.y = (char)((r1 > 0.f) ? 1 : ((r1 < 0.f) ? -1 : 0));
    o.z = (char)((r2 > 0.f) ? 1 : ((r2 < 0.f) ? -1 : 0));
    o.w = (char)((r3 > 0.f) ? 1 : ((r3 < 0.f) ? -1 : 0));
    ((char4*)out)[idx] = o;
}

// BN + 2x2 maxpool + sign, int8 input (stage 2->3). 4 ch/thread.
template <int H, int C>
__global__ void bn_pool_sign4_i8_kernel(const int8_t* __restrict__ y,
                                        int8_t* __restrict__ out,
                                        const float* __restrict__ beta,
                                        int total4) {
    int idx = blockIdx.x * 256 + threadIdx.x;
    if (idx >= total4) return;
    constexpr int Ho = H / 2;
    int e = idx * 4;
    int c = e % C;
    int t = e / C;
    int ox = t % Ho; t /= Ho;
    int oy = t % Ho;
    int b  = t / Ho;
    float4 m  = *(const float4*)(g_mean + c);
    float4 s  = *(const float4*)(g_scale + c);
    float4 bt = *(const float4*)(beta + c);
    size_t base = (((size_t)b * H + 2 * oy) * H + 2 * ox) * C + c;
    char4 u0 = *(const char4*)(y + base);
    char4 u1 = *(const char4*)(y + base + C);
    char4 u2 = *(const char4*)(y + base + (size_t)H * C);
    char4 u3 = *(const char4*)(y + base + (size_t)H * C + C);
    float r0 = fmaxf(fmaxf(((float)u0.x - m.x) * s.x, ((float)u1.x - m.x) * s.x),
                     fmaxf(((float)u2.x - m.x) * s.x, ((float)u3.x - m.x) * s.x)) + bt.x;
    float r1 = fmaxf(fmaxf(((float)u0.y - m.y) * s.y, ((float)u1.y - m.y) * s.y),
                     fmaxf(((float)u2.y - m.y) * s.y, ((float)u3.y - m.y) * s.y)) + bt.y;
    float r2 = fmaxf(fmaxf(((float)u0.z - m.z) * s.z, ((float)u1.z - m.z) * s.z),
                     fmaxf(((float)u2.z - m.z) * s.z, ((float)u3.z - m.z) * s.z)) + bt.z;
    float r3 = fmaxf(fmaxf(((float)u0.w - m.w) * s.w, ((float)u1.w - m.w) * s.w),
                     fmaxf(((float)u2.w - m.w) * s.w, ((float)u3.w - m.w) * s.w)) + bt.w;
    char4 o;
    o.x = (char)((r0 > 0.f) ? 1 : ((r0 < 0.f) ? -1 : 0));
    o.y = (char)((r1 > 0.f) ? 1 : ((r1 < 0.f) ? -1 : 0));
    o.z = (char)((r2 > 0.f) ? 1 : ((r2 < 0.f) ? -1 : 0));
    o.w = (char)((r3 > 0.f) ? 1 : ((r3 < 0.f) ? -1 : 0));
    ((char4*)out)[idx] = o;
}

// ---------------------------------------------------------------------------
// Grouped 4x4 binary conv: int16-pair LDS + dp4a (R8 version, 448us proven).
// ---------------------------------------------------------------------------
template <int H, int C>
__global__ void conv_grp_kernel(const int8_t* __restrict__ a,
                                const int8_t* __restrict__ wg,
                                int8_t* __restrict__ out, int NS) {
    int b = blockIdx.y, oy = blockIdx.x;
    int tid = threadIdx.x;
    constexpr int PW = H + 3;
    __shared__ __align__(16) int8_t as[4][PW][C];
    __shared__ int2 sred[256];

    const int8_t* abase = a + (size_t)b * H * H * C;
    int total4 = (4 * PW * C) / 4;
    for (int i = tid; i < total4; i += 256) {
        int e = i * 4;
        int cc = e % C;
        int col = (e / C) % PW;
        int r = e / (C * PW);
        int ix = col - 1, iy = oy - 1 + r;
        int v = 0;
        if (ix >= 0 && ix < H && iy >= 0 && iy < H)
            v = *(const int*)(abase + ((size_t)iy * H + ix) * C + cc);
        *(int*)(&as[r][col][cc]) = v;
    }

    int c = tid % C;
    int xq = tid / C;
    int g2 = c & ~1;
    int wpair[16];
#pragma unroll
    for (int k = 0; k < 16; k++) {
        int w0 = (int)wg[k * C + c];
        int w1 = (int)wg[(16 + k) * C + c];
        wpair[k] = (w0 & 0xff) | ((w1 & 0xff) << 8);
    }
    __syncthreads();

    int is1 = 0, is2 = 0;
    constexpr int SPAN = (H * C) / 256;
    for (int j = 0; j < SPAN; j++) {
        int ox = xq * SPAN + j;
        int acc = 0;
#pragma unroll
        for (int kh = 0; kh < 4; kh++) {
#pragma unroll
            for (int kw = 0; kw < 4; kw++) {
                int v = (int)*(const uint16_t*)&as[kh][ox + kw][g2];
                acc = __dp4a(v, wpair[kh * 4 + kw], acc);
            }
        }
        out[(((size_t)b * H + oy) * H + ox) * C + c] = (int8_t)acc;
        is1 += acc;
        is2 += acc * acc;
    }

    int slice = b * gridDim.x + blockIdx.x;
    if (C == 256) {
        g_part[(size_t)c * NS + slice]       = (float)is1;
        g_part[(size_t)(C + c) * NS + slice] = (float)is2;
    } else {
        sred[tid] = make_int2(is1, is2);
        __syncthreads();
        if (tid < C) {
            int a1 = 0, a2 = 0;
#pragma unroll
            for (int q = 0; q < 256 / C; q++) {
                a1 += sred[q * C + tid].x;
                a2 += sred[q * C + tid].y;
            }
            g_part[(size_t)tid * NS + slice]       = (float)a1;
            g_part[(size_t)(C + tid) * NS + slice] = (float)a2;
        }
    }
}

// ---------------------------------------------------------------------------
// 1x1 binary conv as dp4a GEMM with FUSED bn+sign on the input tile.
// gemm64: y2b [P,64] -(bn2_1+sign)-> x wp2 [256,64] -> y3b [P,256] int8.
// ---------------------------------------------------------------------------
__global__ void gemm64_kernel(const int8_t* __restrict__ yin,
                              const int8_t* __restrict__ wp,
                              const float* __restrict__ beta,
                              int8_t* __restrict__ out) {
    const int NS = 1024;
    __shared__ __align__(16) int as[128][16];
    __shared__ float pm[64], ps[64], pb[64];
    int tid = threadIdx.x;
    if (tid < 64) {
        pm[tid] = g_mean[tid];
        ps[tid] = g_scale[tid];
        pb[tid] = beta[tid];
    }
    int c = tid;
    int wr[16];
    const int* w4 = (const int*)wp + c * 16;
#pragma unroll
    for (int k = 0; k < 16; k++) wr[k] = w4[k];
    __syncthreads();

    size_t p0 = (size_t)blockIdx.x * 128;
    const int* y4 = (const int*)(yin + p0 * 64);
    for (int i = tid; i < 2048; i += 256) {
        int c0 = (i & 15) * 4;
        int v = y4[i];
        float r0 = ((float)(char)(v)       - pm[c0])     * ps[c0]     + pb[c0];
        float r1 = ((float)(char)(v >> 8)  - pm[c0 + 1]) * ps[c0 + 1] + pb[c0 + 1];
        float r2 = ((float)(char)(v >> 16) - pm[c0 + 2]) * ps[c0 + 2] + pb[c0 + 2];
        float r3 = ((float)(char)(v >> 24) - pm[c0 + 3]) * ps[c0 + 3] + pb[c0 + 3];
        int u0 = (r0 > 0.f) ? 1 : ((r0 < 0.f) ? -1 : 0);
        int u1 = (r1 > 0.f) ? 1 : ((r1 < 0.f) ? -1 : 0);
        int u2 = (r2 > 0.f) ? 1 : ((r2 < 0.f) ? -1 : 0);
        int u3 = (r3 > 0.f) ? 1 : ((r3 < 0.f) ? -1 : 0);
        as[i >> 4][i & 15] =
            (u0 & 0xff) | ((u1 & 0xff) << 8) | ((u2 & 0xff) << 16) | (u3 << 24);
    }
    __syncthreads();

    int is1 = 0, is2 = 0;
    for (int p = 0; p < 128; p++) {
        int acc = 0;
        const int4* av = (const int4*)as[p];
#pragma unroll
        for (int k4 = 0; k4 < 4; k4++) {
            int4 v = av[k4];
            acc = __dp4a(v.x, wr[k4 * 4 + 0], acc);
            acc = __dp4a(v.y, wr[k4 * 4 + 1], acc);
            acc = __dp4a(v.z, wr[k4 * 4 + 2], acc);
            acc = __dp4a(v.w, wr[k4 * 4 + 3], acc);
        }
        out[(p0 + p) * 256 + c] = (int8_t)acc;
        is1 += acc;
        is2 += acc * acc;
    }
    g_part[(size_t)c * NS + blockIdx.x]         = (float)is1;
    g_part[(size_t)(256 + c) * NS + blockIdx.x] = (float)is2;
}

// gemm256: y4b [P,256] -(bn3_1+sign)-> x wp3 [256,256] -> y5s [P,256] int16.
__global__ void gemm256_kernel(const int8_t* __restrict__ yin,
                               const int8_t* __restrict__ wp,
                               const float* __restrict__ beta,
                               int16_t* __restrict__ out) {
    const int NS = 512;
    __shared__ __align__(16) int as[64][64];
    __shared__ float pm[256], ps[256], pb[256];
    int tid = threadIdx.x;
    pm[tid] = g_mean[tid];
    ps[tid] = g_scale[tid];
    pb[tid] = beta[tid];
    int c = tid;
    int wr[64];
    const int* w4 = (const int*)wp + c * 64;
#pragma unroll
    for (int k = 0; k < 64; k++) wr[k] = w4[k];
    __syncthreads();

    size_t p0 = (size_t)blockIdx.x * 64;
    const int* y4 = (const int*)(yin + p0 * 256);
    for (int i = tid; i < 4096; i += 256) {
        int c0 = (i & 63) * 4;
        int v = y4[i];
        float r0 = ((float)(char)(v)       - pm[c0])     * ps[c0]     + pb[c0];
        float r1 = ((float)(char)(v >> 8)  - pm[c0 + 1]) * ps[c0 + 1] + pb[c0 + 1];
        float r2 = ((float)(char)(v >> 16) - pm[c0 + 2]) * ps[c0 + 2] + pb[c0 + 2];
        float r3 = ((float)(char)(v >> 24) - pm[c0 + 3]) * ps[c0 + 3] + pb[c0 + 3];
        int u0 = (r0 > 0.f) ? 1 : ((r0 < 0.f) ? -1 : 0);
        int u1 = (r1 > 0.f) ? 1 : ((r1 < 0.f) ? -1 : 0);
        int u2 = (r2 > 0.f) ? 1 : ((r2 < 0.f) ? -1 : 0);
        int u3 = (r3 > 0.f) ? 1 : ((r3 < 0.f) ? -1 : 0);
        as[i >> 6][i & 63] =
            (u0 & 0xff) | ((u1 & 0xff) << 8) | ((u2 & 0xff) << 16) | (u3 << 24);
    }
    __syncthreads();

    int is1 = 0, is2 = 0;
    for (int p = 0; p < 64; p++) {
        int acc = 0;
        const int4* av = (const int4*)as[p];
#pragma unroll
        for (int k4 = 0; k4 < 16; k4++) {
            int4 v = av[k4];
            acc = __dp4a(v.x, wr[k4 * 4 + 0], acc);
            acc = __dp4a(v.y, wr[k4 * 4 + 1], acc);
            acc = __dp4a(v.z, wr[k4 * 4 + 2], acc);
            acc = __dp4a(v.w, wr[k4 * 4 + 3], acc);
        }
        out[(p0 + p) * 256 + c] = (int16_t)acc;
        is1 += acc;
        is2 += acc * acc;
    }
    g_part[(size_t)c * NS + blockIdx.x]         = (float)is1;
    g_part[(size_t)(256 + c) * NS + blockIdx.x] = (float)is2;
}

// ---------------------------------------------------------------------------
// FC with fused bn3_2; 4 batches per block; int16 input.
// ---------------------------------------------------------------------------
#define FCB 4
__global__ void fc_kernel(const int16_t* __restrict__ y5,
                          const float* __restrict__ fcwr,
                          const float* __restrict__ fc_b,
                          const float* __restrict__ beta,
                          float* __restrict__ out) {
    int b0 = blockIdx.x * FCB;
    int tid = threadIdx.x;
    float acc[FCB][10];
#pragma unroll
    for (int bb = 0; bb < FCB; bb++)
#pragma unroll
        for (int n = 0; n < 10; n++) acc[bb][n] = 0.f;

    for (int i = tid; i < 16384; i += 256) {
        int c = i & 255;
        float m = g_mean[c], s = g_scale[c], bt = beta[c];
        float w[10];
#pragma unroll
        for (int n = 0; n < 10; n++) w[n] = fcwr[n * 16384 + i];
#pragma unroll
        for (int bb = 0; bb < FCB; bb++) {
            float v = ((float)y5[(size_t)(b0 + bb) * 16384 + i] - m) * s + bt;
#pragma unroll
            for (int n = 0; n < 10; n++) acc[bb][n] += v * w[n];
        }
    }

    __shared__ float sred[8][FCB * 10];
    int lane = tid & 31, wid = tid >> 5;
#pragma unroll
    for (int bb = 0; bb < FCB; bb++)
#pragma unroll
        for (int n = 0; n < 10; n++) {
            float v = acc[bb][n];
#pragma unroll
            for (int o = 16; o > 0; o >>= 1)
                v += __shfl_xor_sync(0xffffffffu, v, o);
            if (lane == 0) sred[wid][bb * 10 + n] = v;
        }
    __syncthreads();
    if (tid < FCB * 10) {
        float v = 0.f;
#pragma unroll
        for (int w8 = 0; w8 < 8; w8++) v += sred[w8][tid];
        int bb = tid / 10, n = tid % 10;
        out[(b0 + bb) * 10 + n] = v + fc_b[n];
    }
}

// ---------------------------------------------------------------------------
extern "C" void kernel_launch(void* const* d_in, const int* in_sizes, int n_in,
                              void* d_out, int out_size) {
    const float* x    = (const float*)d_in[0];
    const float* w1   = (const float*)d_in[1];
    const float* g1   = (const float*)d_in[2];
    const float* b1   = (const float*)d_in[3];
    const float* w2_1 = (const float*)d_in[4];
    const float* g2_1 = (const float*)d_in[5];
    const float* b2_1 = (const float*)d_in[6];
    const float* w2_2 = (const float*)d_in[7];
    const float* g2_2 = (const float*)d_in[8];
    const float* b2_2 = (const float*)d_in[9];
    const float* w3_1 = (const float*)d_in[10];
    const float* g3_1 = (const float*)d_in[11];
    const float* b3_1 = (const float*)d_in[12];
    const float* w3_2 = (const float*)d_in[13];
    const float* g3_2 = (const float*)d_in[14];
    const float* b3_2 = (const float*)d_in[15];
    const float* fcw  = (const float*)d_in[16];
    const float* fcb  = (const float*)d_in[17];
    float* out = (float*)d_out;

    float *y1, *fcwr, *w1s;
    int8_t *a1, *a3, *y2b, *y3b, *y4b, *wp2, *wp3, *wg2, *wg3;
    int16_t *y5s;
    cudaGetSymbolAddress((void**)&y1, g_y1);
    cudaGetSymbolAddress((void**)&y2b, g_y2b);
    cudaGetSymbolAddress((void**)&y3b, g_y3b);
    cudaGetSymbolAddress((void**)&y4b, g_y4b);
    cudaGetSymbolAddress((void**)&y5s, g_y5s);
    cudaGetSymbolAddress((void**)&a1, g_a1);
    cudaGetSymbolAddress((void**)&a3, g_a3);
    cudaGetSymbolAddress((void**)&wp2, g_wp2);
    cudaGetSymbolAddress((void**)&wp3, g_wp3);
    cudaGetSymbolAddress((void**)&wg2, g_wg2);
    cudaGetSymbolAddress((void**)&wg3, g_wg3);
    cudaGetSymbolAddress((void**)&fcwr, g_fcwr);
    cudaGetSymbolAddress((void**)&w1s, g_w1s);

    // 1: all weight prep
    prep_kernel<<<1012, 256>>>(w1, w2_1, w3_1, w2_2, w3_2, fcw,
                               w1s, wg2, wg3, wp2, wp3, fcwr);

    // 2-4: stage 1 (bn_pool_sign4_f stays in profiled slot 4)
    conv1_kernel<<<dim3(8, BATCH), 256>>>(x, w1s, y1);
    reduce_finalize_kernel<64><<<64, 256>>>(g1, 4096, 512 * 1024);
    bn_pool_sign4_f_kernel<32, 64><<<(512 * 256 * 64 / 4 + 255) / 256, 256>>>(
        y1, a1, b1, 512 * 256 * 64 / 4);

    // 5-9: stage 2
    conv_grp_kernel<16, 64><<<dim3(16, BATCH), 256>>>(a1, wg2, y2b, 8192);
    reduce_finalize_kernel<64><<<64, 256>>>(g2_1, 8192, 512 * 256);
    gemm64_kernel<<<(512 * 256) / 128, 256>>>(y2b, wp2, b2_1, y3b);
    reduce_finalize_kernel<256><<<256, 256>>>(g2_2, 1024, 512 * 256);
    bn_pool_sign4_i8_kernel<16, 256><<<(512 * 64 * 256 / 4 + 255) / 256, 256>>>(
        y3b, a3, b2_2, 512 * 64 * 256 / 4);

    // 10-13: stage 3
    conv_grp_kernel<8, 256><<<dim3(8, BATCH), 256>>>(a3, wg3, y4b, 4096);
    reduce_finalize_kernel<256><<<256, 256>>>(g3_1, 4096, 512 * 64);
    gemm256_kernel<<<(512 * 64) / 64, 256>>>(y4b, wp3, b3_1, y5s);
    reduce_finalize_kernel<256><<<256, 256>>>(g3_2, 512, 512 * 64);

    // 14: FC (bn3_2 fused)
    fc_kernel<<<BATCH / FCB, 256>>>(y5s, fcwr, fcb, b3_2, out);
}

// round 10
// speedup vs baseline: 1.4829x; 1.0532x over previous
#include <cuda_runtime.h>
#include <cstdint>
#include <cstdio>

// ---------------------------------------------------------------------------
// LiBNet forward, batch 512.  Round 10 = R9 (427us) + pre-pool (max,min) in
// producers: conv1 and gemm64 emit per-2x2-window max AND min; BN kernels
// select by sign(scale) (exact: max commutes with positive affine, min with
// negative). Halves y1/y3 HBM round trips.
// ---------------------------------------------------------------------------

#define BATCH 512

// Scratch (device globals)
__device__ float   g_y1mx[512u*256u*64u];  // conv1 window max [b,16,16,64]
__device__ float   g_y1mn[512u*256u*64u];  // conv1 window min
__device__ int8_t  g_a1[512u*256u*64u];    // sign(pool(bn1)) [b,16,16,64]
__device__ int8_t  g_y2b[512u*256u*64u];   // conv2_1 out int8
__device__ int8_t  g_y3mx[512u*64u*256u];  // gemm64 window max [b,8,8,256]
__device__ int8_t  g_y3mn[512u*64u*256u];  // gemm64 window min
__device__ int8_t  g_a3[512u*64u*256u];    // sign(pool(bn2_2)) [b,8,8,256]
__device__ int8_t  g_y4b[512u*64u*256u];   // conv3_1 out int8
__device__ int16_t g_y5s[512u*64u*256u];   // conv3_2 out int16
__device__ float   g_w1s[48*64];           // sign(w1) transposed [k][c]
__device__ int8_t  g_wg2[32*64];           // sign(w2_1) transposed [k][c]
__device__ int8_t  g_wg3[32*256];          // sign(w3_1) transposed [k][c]
__device__ int8_t  g_wp2[256*64];          // sign(w2_2)
__device__ int8_t  g_wp3[256*256];         // sign(w3_2)
__device__ float   g_part[2097152];        // stats partials [c][slice]
__device__ float   g_mean[256];
__device__ float   g_scale[256];
__device__ float   g_fcwr[16384*10];       // fc_w n-major over NHWC-flatten

// ---------------------------------------------------------------------------
// prep: all weight packing in one kernel (block ranges; each range exact).
// ---------------------------------------------------------------------------
__global__ void prep_kernel(const float* __restrict__ w1,
                            const float* __restrict__ w2_1,
                            const float* __restrict__ w3_1,
                            const float* __restrict__ w2_2,
                            const float* __restrict__ w3_2,
                            const float* __restrict__ fcw,
                            float* __restrict__ w1s,
                            int8_t* __restrict__ wg2,
                            int8_t* __restrict__ wg3,
                            int8_t* __restrict__ wp2,
                            int8_t* __restrict__ wp3,
                            float* __restrict__ fcwr) {
    int bid = blockIdx.x, tid = threadIdx.x;
    if (bid < 640) {
        int i = bid * 256 + tid;  // i = n*16384 + e, e = hw*256 + c
        int n = i / 16384;
        int e = i % 16384;
        int c = e & 255, hw = e >> 8;
        fcwr[i] = fcw[n * 16384 + c * 64 + hw];
    } else if (bid < 896) {
        int i = (bid - 640) * 256 + tid;
        float v = w3_2[i];
        wp3[i] = (int8_t)((v > 0.f) ? 1 : ((v < 0.f) ? -1 : 0));
    } else if (bid < 960) {
        int i = (bid - 896) * 256 + tid;
        float v = w2_2[i];
        wp2[i] = (int8_t)((v > 0.f) ? 1 : ((v < 0.f) ? -1 : 0));
    } else if (bid < 992) {
        int i = (bid - 960) * 256 + tid;  // i = k*256 + c
        int c = i & 255, k = i >> 8;
        float v = w3_1[c * 32 + k];
        wg3[i] = (int8_t)((v > 0.f) ? 1 : ((v < 0.f) ? -1 : 0));
    } else if (bid < 1000) {
        int i = (bid - 992) * 256 + tid;  // i = k*64 + c
        int c = i & 63, k = i >> 6;
        float v = w2_1[c * 32 + k];
        wg2[i] = (int8_t)((v > 0.f) ? 1 : ((v < 0.f) ? -1 : 0));
    } else {
        int i = (bid - 1000) * 256 + tid;  // i = k*64 + c
        int c = i & 63, k = i >> 6;
        float v = w1[c * 48 + k];
        w1s[i] = (v > 0.f) ? 1.f : ((v < 0.f) ? -1.f : 0.f);
    }
}

// ---------------------------------------------------------------------------
// conv1: x [b,3,32,32] NCHW, pad (t1,b2,l1,r2). 4 output rows per block
// (= 2 pool rows, fully thread-local 2x2 windows). Emits window (max,min)
// into [b,16,16,64] + exact fused channel stats over all pre-pool values.
// block: 256 = (c 0..63, xq 0..3); grid (8, B).
// ---------------------------------------------------------------------------
__global__ void conv1_kernel(const float* __restrict__ x,
                             const float* __restrict__ w1s,
                             float* __restrict__ ymx,
                             float* __restrict__ ymn) {
    const int NS = 4096;  // 8 * 512 slices
    int b = blockIdx.y, oy0 = blockIdx.x * 4;
    int tid = threadIdx.x;
    int c = tid & 63, xq = tid >> 6;

    __shared__ float xs[3][7][36];
    __shared__ float2 sred[256];

    for (int i = tid; i < 3 * 7 * 36; i += 256) {
        int col = i % 36;
        int r   = (i / 36) % 7;
        int ci  = i / 252;
        int ix = col - 1, iy = oy0 - 1 + r;
        float v = 0.f;
        if (ix >= 0 && ix < 32 && iy >= 0 && iy < 32)
            v = x[(((size_t)b * 3 + ci) * 32 + iy) * 32 + ix];
        xs[ci][r][col] = v;
    }

    float wr[48];
#pragma unroll
    for (int k = 0; k < 48; k++) wr[k] = w1s[k * 64 + c];
    __syncthreads();

    float s1 = 0.f, s2 = 0.f;
    float pmx[4], pmn[4];  // horizontal-pair max/min carried from even row
#pragma unroll
    for (int r = 0; r < 4; r++) {
        float acc[8];
#pragma unroll
        for (int j = 0; j < 8; j++) acc[j] = 0.f;
#pragma unroll
        for (int ci = 0; ci < 3; ci++) {
#pragma unroll
            for (int kh = 0; kh < 4; kh++) {
                float rx[11];
#pragma unroll
                for (int t = 0; t < 11; t++) rx[t] = xs[ci][r + kh][xq * 8 + t];
#pragma unroll
                for (int kw = 0; kw < 4; kw++) {
                    float wv = wr[ci * 16 + kh * 4 + kw];
#pragma unroll
                    for (int j = 0; j < 8; j++) acc[j] += wv * rx[j + kw];
                }
            }
        }
#pragma unroll
        for (int j = 0; j < 8; j++) {
            s1 += acc[j];
            s2 += acc[j] * acc[j];
        }
        if ((r & 1) == 0) {
#pragma unroll
            for (int p = 0; p < 4; p++) {
                pmx[p] = fmaxf(acc[2 * p], acc[2 * p + 1]);
                pmn[p] = fminf(acc[2 * p], acc[2 * p + 1]);
            }
        } else {
            int poy = (oy0 >> 1) + (r >> 1);
#pragma unroll
            for (int p = 0; p < 4; p++) {
                float wmx = fmaxf(pmx[p], fmaxf(acc[2 * p], acc[2 * p + 1]));
                float wmn = fminf(pmn[p], fminf(acc[2 * p], acc[2 * p + 1]));
                size_t oi = (((size_t)b * 16 + poy) * 16 + xq * 4 + p) * 64 + c;
                ymx[oi] = wmx;
                ymn[oi] = wmn;
            }
        }
    }

    sred[tid] = make_float2(s1, s2);
    __syncthreads();
    if (tid < 64) {
        float2 a = sred[tid], b1 = sred[tid + 64], c1 = sred[tid + 128],
               d1 = sred[tid + 192];
        int slice = b * 8 + blockIdx.x;
        g_part[tid * NS + slice]        = a.x + b1.x + c1.x + d1.x;
        g_part[(64 + tid) * NS + slice] = a.y + b1.y + c1.y + d1.y;
    }
}

// ---------------------------------------------------------------------------
// Reduce partials (coalesced: [c][slice]) + shift-BN finalize.
// ---------------------------------------------------------------------------
template <int C>
__global__ void reduce_finalize_kernel(const float* __restrict__ gamma,
                                       int nslices, int P) {
    int c = blockIdx.x;
    int tid = threadIdx.x;
    float s1 = 0.f, s2 = 0.f;
    const float* p1 = g_part + (size_t)c * nslices;
    const float* p2 = g_part + (size_t)(C + c) * nslices;
#pragma unroll 4
    for (int s = tid; s < nslices; s += 256) {
        s1 += p1[s];
        s2 += p2[s];
    }
    __shared__ double sd1[256], sd2[256];
    sd1[tid] = (double)s1;
    sd2[tid] = (double)s2;
    __syncthreads();
    for (int s = 128; s > 0; s >>= 1) {
        if (tid < s) {
            sd1[tid] += sd1[tid + s];
            sd2[tid] += sd2[tid + s];
        }
        __syncthreads();
    }
    if (tid == 0) {
        double mean = sd1[0] / (double)P;
        double var  = sd2[0] / (double)P - mean * mean;
        double inv  = (double)gamma[c] / sqrt(var + 1e-5);
        double sh   = rint(log2(fabs(inv) + 1e-12));
        if (sh > 4.0) sh = 4.0;
        if (sh < -4.0) sh = -4.0;
        double sgn = (inv > 0.0) ? 1.0 : ((inv < 0.0) ? -1.0 : 0.0);
        g_mean[c]  = (float)mean;
        g_scale[c] = (float)(sgn * exp2(sh));
    }
}

// ---------------------------------------------------------------------------
// BN + pool-select + sign, fp32 (max,min) input. 4 ch/thread.
// pooled value = (s>0 ? max : min); r = (v-m)*s + beta; sign.
// ---------------------------------------------------------------------------
__global__ void bn_poolsel_sign4_f_kernel(const float* __restrict__ ymx,
                                          const float* __restrict__ ymn,
                                          int8_t* __restrict__ out,
                                          const float* __restrict__ beta,
                                          int total4) {
    int idx = blockIdx.x * 256 + threadIdx.x;
    if (idx >= total4) return;
    int c = (idx * 4) & 63;
    float4 m  = *(const float4*)(g_mean + c);
    float4 s  = *(const float4*)(g_scale + c);
    float4 bt = *(const float4*)(beta + c);
    float4 vx = ((const float4*)ymx)[idx];
    float4 vn = ((const float4*)ymn)[idx];
    float v0 = (s.x > 0.f) ? vx.x : vn.x;
    float v1 = (s.y > 0.f) ? vx.y : vn.y;
    float v2 = (s.z > 0.f) ? vx.z : vn.z;
    float v3 = (s.w > 0.f) ? vx.w : vn.w;
    float r0 = (v0 - m.x) * s.x + bt.x;
    float r1 = (v1 - m.y) * s.y + bt.y;
    float r2 = (v2 - m.z) * s.z + bt.z;
    float r3 = (v3 - m.w) * s.w + bt.w;
    char4 o;
    o.x = (char)((r0 > 0.f) ? 1 : ((r0 < 0.f) ? -1 : 0));
    o.y = (char)((r1 > 0.f) ? 1 : ((r1 < 0.f) ? -1 : 0));
    o.z = (char)((r2 > 0.f) ? 1 : ((r2 < 0.f) ? -1 : 0));
    o.w = (char)((r3 > 0.f) ? 1 : ((r3 < 0.f) ? -1 : 0));
    ((char4*)out)[idx] = o;
}

// BN + pool-select + sign, int8 (max,min) input. 4 ch/thread, C=256.
__global__ void bn_poolsel_sign4_i8_kernel(const int8_t* __restrict__ ymx,
                                           const int8_t* __restrict__ ymn,
                                           int8_t* __restrict__ out,
                                           const float* __restrict__ beta,
                                           int total4) {
    int idx = blockIdx.x * 256 + threadIdx.x;
    if (idx >= total4) return;
    int c = (idx * 4) & 255;
    float4 m  = *(const float4*)(g_mean + c);
    float4 s  = *(const float4*)(g_scale + c);
    float4 bt = *(const float4*)(beta + c);
    char4 ux = ((const char4*)ymx)[idx];
    char4 un = ((const char4*)ymn)[idx];
    float v0 = (float)((s.x > 0.f) ? ux.x : un.x);
    float v1 = (float)((s.y > 0.f) ? ux.y : un.y);
    float v2 = (float)((s.z > 0.f) ? ux.z : un.z);
    float v3 = (float)((s.w > 0.f) ? ux.w : un.w);
    float r0 = (v0 - m.x) * s.x + bt.x;
    float r1 = (v1 - m.y) * s.y + bt.y;
    float r2 = (v2 - m.z) * s.z + bt.z;
    float r3 = (v3 - m.w) * s.w + bt.w;
    char4 o;
    o.x = (char)((r0 > 0.f) ? 1 : ((r0 < 0.f) ? -1 : 0));
    o.y = (char)((r1 > 0.f) ? 1 : ((r1 < 0.f) ? -1 : 0));
    o.z = (char)((r2 > 0.f) ? 1 : ((r2 < 0.f) ? -1 : 0));
    o.w = (char)((r3 > 0.f) ? 1 : ((r3 < 0.f) ? -1 : 0));
    ((char4*)out)[idx] = o;
}

// ---------------------------------------------------------------------------
// Grouped 4x4 binary conv: int16-pair LDS + dp4a (R8 version, proven).
// ---------------------------------------------------------------------------
template <int H, int C>
__global__ void conv_grp_kernel(const int8_t* __restrict__ a,
                                const int8_t* __restrict__ wg,
                                int8_t* __restrict__ out, int NS) {
    int b = blockIdx.y, oy = blockIdx.x;
    int tid = threadIdx.x;
    constexpr int PW = H + 3;
    __shared__ __align__(16) int8_t as[4][PW][C];
    __shared__ int2 sred[256];

    const int8_t* abase = a + (size_t)b * H * H * C;
    int total4 = (4 * PW * C) / 4;
    for (int i = tid; i < total4; i += 256) {
        int e = i * 4;
        int cc = e % C;
        int col = (e / C) % PW;
        int r = e / (C * PW);
        int ix = col - 1, iy = oy - 1 + r;
        int v = 0;
        if (ix >= 0 && ix < H && iy >= 0 && iy < H)
            v = *(const int*)(abase + ((size_t)iy * H + ix) * C + cc);
        *(int*)(&as[r][col][cc]) = v;
    }

    int c = tid % C;
    int xq = tid / C;
    int g2 = c & ~1;
    int wpair[16];
#pragma unroll
    for (int k = 0; k < 16; k++) {
        int w0 = (int)wg[k * C + c];
        int w1 = (int)wg[(16 + k) * C + c];
        wpair[k] = (w0 & 0xff) | ((w1 & 0xff) << 8);
    }
    __syncthreads();

    int is1 = 0, is2 = 0;
    constexpr int SPAN = (H * C) / 256;
    for (int j = 0; j < SPAN; j++) {
        int ox = xq * SPAN + j;
        int acc = 0;
#pragma unroll
        for (int kh = 0; kh < 4; kh++) {
#pragma unroll
            for (int kw = 0; kw < 4; kw++) {
                int v = (int)*(const uint16_t*)&as[kh][ox + kw][g2];
                acc = __dp4a(v, wpair[kh * 4 + kw], acc);
            }
        }
        out[(((size_t)b * H + oy) * H + ox) * C + c] = (int8_t)acc;
        is1 += acc;
        is2 += acc * acc;
    }

    int slice = b * gridDim.x + blockIdx.x;
    if (C == 256) {
        g_part[(size_t)c * NS + slice]       = (float)is1;
        g_part[(size_t)(C + c) * NS + slice] = (float)is2;
    } else {
        sred[tid] = make_int2(is1, is2);
        __syncthreads();
        if (tid < C) {
            int a1 = 0, a2 = 0;
#pragma unroll
            for (int q = 0; q < 256 / C; q++) {
                a1 += sred[q * C + tid].x;
                a2 += sred[q * C + tid].y;
            }
            g_part[(size_t)tid * NS + slice]       = (float)a1;
            g_part[(size_t)(C + tid) * NS + slice] = (float)a2;
        }
    }
}

// ---------------------------------------------------------------------------
// gemm64: y2b [P,64] -(bn2_1+sign in loader)-> x wp2 [256,64], with 2x2
// PRE-POOL: emits per-window (max,min) int8 into [b,8,8,256] + exact stats.
// Block = 128 consecutive positions = 8 rows x 16 cols of one image half.
// Each thread owns channel c for all 128 positions -> windows thread-local.
// ---------------------------------------------------------------------------
__global__ void gemm64_kernel(const int8_t* __restrict__ yin,
                              const int8_t* __restrict__ wp,
                              const float* __restrict__ beta,
                              int8_t* __restrict__ omx,
                              int8_t* __restrict__ omn) {
    const int NS = 1024;
    __shared__ __align__(16) int as[128][16];
    __shared__ float pm[64], ps[64], pb[64];
    int tid = threadIdx.x;
    if (tid < 64) {
        pm[tid] = g_mean[tid];
        ps[tid] = g_scale[tid];
        pb[tid] = beta[tid];
    }
    int c = tid;
    int wr[16];
    const int* w4 = (const int*)wp + c * 16;
#pragma unroll
    for (int k = 0; k < 16; k++) wr[k] = w4[k];
    __syncthreads();

    size_t p0 = (size_t)blockIdx.x * 128;
    const int* y4 = (const int*)(yin + p0 * 64);
    for (int i = tid; i < 2048; i += 256) {
        int c0 = (i & 15) * 4;
        int v = y4[i];
        float r0 = ((float)(char)(v)       - pm[c0])     * ps[c0]     + pb[c0];
        float r1 = ((float)(char)(v >> 8)  - pm[c0 + 1]) * ps[c0 + 1] + pb[c0 + 1];
        float r2 = ((float)(char)(v >> 16) - pm[c0 + 2]) * ps[c0 + 2] + pb[c0 + 2];
        float r3 = ((float)(char)(v >> 24) - pm[c0 + 3]) * ps[c0 + 3] + pb[c0 + 3];
        int u0 = (r0 > 0.f) ? 1 : ((r0 < 0.f) ? -1 : 0);
        int u1 = (r1 > 0.f) ? 1 : ((r1 < 0.f) ? -1 : 0);
        int u2 = (r2 > 0.f) ? 1 : ((r2 < 0.f) ? -1 : 0);
        int u3 = (r3 > 0.f) ? 1 : ((r3 < 0.f) ? -1 : 0);
        as[i >> 4][i & 15] =
            (u0 & 0xff) | ((u1 & 0xff) << 8) | ((u2 & 0xff) << 16) | (u3 << 24);
    }
    __syncthreads();

    // block geometry: b = bid/2, rows row0..row0+7 where row0 = (bid&1)*8
    int bimg = blockIdx.x >> 1;
    int prow0 = (blockIdx.x & 1) * 4;  // pooled row base
    int is1 = 0, is2 = 0;
    int rpx[8], rpn[8];
    for (int lr = 0; lr < 8; lr++) {
#pragma unroll
        for (int cp = 0; cp < 8; cp++) {
            int a0, a1;
#pragma unroll
            for (int h = 0; h < 2; h++) {
                int p = lr * 16 + cp * 2 + h;
                int acc = 0;
                const int4* av = (const int4*)as[p];
#pragma unroll
                for (int k4 = 0; k4 < 4; k4++) {
                    int4 v = av[k4];
                    acc = __dp4a(v.x, wr[k4 * 4 + 0], acc);
                    acc = __dp4a(v.y, wr[k4 * 4 + 1], acc);
                    acc = __dp4a(v.z, wr[k4 * 4 + 2], acc);
                    acc = __dp4a(v.w, wr[k4 * 4 + 3], acc);
                }
                is1 += acc;
                is2 += acc * acc;
                if (h == 0) a0 = acc; else a1 = acc;
            }
            int hx = max(a0, a1), hn = min(a0, a1);
            if ((lr & 1) == 0) {
                rpx[cp] = hx;
                rpn[cp] = hn;
            } else {
                int wmx = max(rpx[cp], hx);
                int wmn = min(rpn[cp], hn);
                size_t oi = (((size_t)bimg * 8 + prow0 + (lr >> 1)) * 8 + cp) * 256 + c;
                omx[oi] = (int8_t)wmx;
                omn[oi] = (int8_t)wmn;
            }
        }
    }
    g_part[(size_t)c * NS + blockIdx.x]         = (float)is1;
    g_part[(size_t)(256 + c) * NS + blockIdx.x] = (float)is2;
}

// gemm256: y4b [P,256] -(bn3_1+sign in loader)-> x wp3 [256,256] -> y5s int16.
__global__ void gemm256_kernel(const int8_t* __restrict__ yin,
                               const int8_t* __restrict__ wp,
                               const float* __restrict__ beta,
                               int16_t* __restrict__ out) {
    const int NS = 512;
    __shared__ __align__(16) int as[64][64];
    __shared__ float pm[256], ps[256], pb[256];
    int tid = threadIdx.x;
    pm[tid] = g_mean[tid];
    ps[tid] = g_scale[tid];
    pb[tid] = beta[tid];
    int c = tid;
    int wr[64];
    const int* w4 = (const int*)wp + c * 64;
#pragma unroll
    for (int k = 0; k < 64; k++) wr[k] = w4[k];
    __syncthreads();

    size_t p0 = (size_t)blockIdx.x * 64;
    const int* y4 = (const int*)(yin + p0 * 256);
    for (int i = tid; i < 4096; i += 256) {
        int c0 = (i & 63) * 4;
        int v = y4[i];
        float r0 = ((float)(char)(v)       - pm[c0])     * ps[c0]     + pb[c0];
        float r1 = ((float)(char)(v >> 8)  - pm[c0 + 1]) * ps[c0 + 1] + pb[c0 + 1];
        float r2 = ((float)(char)(v >> 16) - pm[c0 + 2]) * ps[c0 + 2] + pb[c0 + 2];
        float r3 = ((float)(char)(v >> 24) - pm[c0 + 3]) * ps[c0 + 3] + pb[c0 + 3];
        int u0 = (r0 > 0.f) ? 1 : ((r0 < 0.f) ? -1 : 0);
        int u1 = (r1 > 0.f) ? 1 : ((r1 < 0.f) ? -1 : 0);
        int u2 = (r2 > 0.f) ? 1 : ((r2 < 0.f) ? -1 : 0);
        int u3 = (r3 > 0.f) ? 1 : ((r3 < 0.f) ? -1 : 0);
        as[i >> 6][i & 63] =
            (u0 & 0xff) | ((u1 & 0xff) << 8) | ((u2 & 0xff) << 16) | (u3 << 24);
    }
    __syncthreads();

    int is1 = 0, is2 = 0;
    for (int p = 0; p < 64; p++) {
        int acc = 0;
        const int4* av = (const int4*)as[p];
#pragma unroll
        for (int k4 = 0; k4 < 16; k4++) {
            int4 v = av[k4];
            acc = __dp4a(v.x, wr[k4 * 4 + 0], acc);
            acc = __dp4a(v.y, wr[k4 * 4 + 1], acc);
            acc = __dp4a(v.z, wr[k4 * 4 + 2], acc);
            acc = __dp4a(v.w, wr[k4 * 4 + 3], acc);
        }
        out[(p0 + p) * 256 + c] = (int16_t)acc;
        is1 += acc;
        is2 += acc * acc;
    }
    g_part[(size_t)c * NS + blockIdx.x]         = (float)is1;
    g_part[(size_t)(256 + c) * NS + blockIdx.x] = (float)is2;
}

// ---------------------------------------------------------------------------
// FC with fused bn3_2; 4 batches per block; int16 input.
// ---------------------------------------------------------------------------
#define FCB 4
__global__ void fc_kernel(const int16_t* __restrict__ y5,
                          const float* __restrict__ fcwr,
                          const float* __restrict__ fc_b,
                          const float* __restrict__ beta,
                          float* __restrict__ out) {
    int b0 = blockIdx.x * FCB;
    int tid = threadIdx.x;
    float acc[FCB][10];
#pragma unroll
    for (int bb = 0; bb < FCB; bb++)
#pragma unroll
        for (int n = 0; n < 10; n++) acc[bb][n] = 0.f;

    for (int i = tid; i < 16384; i += 256) {
        int c = i & 255;
        float m = g_mean[c], s = g_scale[c], bt = beta[c];
        float w[10];
#pragma unroll
        for (int n = 0; n < 10; n++) w[n] = fcwr[n * 16384 + i];
#pragma unroll
        for (int bb = 0; bb < FCB; bb++) {
            float v = ((float)y5[(size_t)(b0 + bb) * 16384 + i] - m) * s + bt;
#pragma unroll
            for (int n = 0; n < 10; n++) acc[bb][n] += v * w[n];
        }
    }

    __shared__ float sred[8][FCB * 10];
    int lane = tid & 31, wid = tid >> 5;
#pragma unroll
    for (int bb = 0; bb < FCB; bb++)
#pragma unroll
        for (int n = 0; n < 10; n++) {
            float v = acc[bb][n];
#pragma unroll
            for (int o = 16; o > 0; o >>= 1)
                v += __shfl_xor_sync(0xffffffffu, v, o);
            if (lane == 0) sred[wid][bb * 10 + n] = v;
        }
    __syncthreads();
    if (tid < FCB * 10) {
        float v = 0.f;
#pragma unroll
        for (int w8 = 0; w8 < 8; w8++) v += sred[w8][tid];
        int bb = tid / 10, n = tid % 10;
        out[(b0 + bb) * 10 + n] = v + fc_b[n];
    }
}

// ---------------------------------------------------------------------------
extern "C" void kernel_launch(void* const* d_in, const int* in_sizes, int n_in,
                              void* d_out, int out_size) {
    const float* x    = (const float*)d_in[0];
    const float* w1   = (const float*)d_in[1];
    const float* g1   = (const float*)d_in[2];
    const float* b1   = (const float*)d_in[3];
    const float* w2_1 = (const float*)d_in[4];
    const float* g2_1 = (const float*)d_in[5];
    const float* b2_1 = (const float*)d_in[6];
    const float* w2_2 = (const float*)d_in[7];
    const float* g2_2 = (const float*)d_in[8];
    const float* b2_2 = (const float*)d_in[9];
    const float* w3_1 = (const float*)d_in[10];
    const float* g3_1 = (const float*)d_in[11];
    const float* b3_1 = (const float*)d_in[12];
    const float* w3_2 = (const float*)d_in[13];
    const float* g3_2 = (const float*)d_in[14];
    const float* b3_2 = (const float*)d_in[15];
    const float* fcw  = (const float*)d_in[16];
    const float* fcb  = (const float*)d_in[17];
    float* out = (float*)d_out;

    float *y1mx, *y1mn, *fcwr, *w1s;
    int8_t *a1, *a3, *y2b, *y3mx, *y3mn, *y4b, *wp2, *wp3, *wg2, *wg3;
    int16_t *y5s;
    cudaGetSymbolAddress((void**)&y1mx, g_y1mx);
    cudaGetSymbolAddress((void**)&y1mn, g_y1mn);
    cudaGetSymbolAddress((void**)&y2b, g_y2b);
    cudaGetSymbolAddress((void**)&y3mx, g_y3mx);
    cudaGetSymbolAddress((void**)&y3mn, g_y3mn);
    cudaGetSymbolAddress((void**)&y4b, g_y4b);
    cudaGetSymbolAddress((void**)&y5s, g_y5s);
    cudaGetSymbolAddress((void**)&a1, g_a1);
    cudaGetSymbolAddress((void**)&a3, g_a3);
    cudaGetSymbolAddress((void**)&wp2, g_wp2);
    cudaGetSymbolAddress((void**)&wp3, g_wp3);
    cudaGetSymbolAddress((void**)&wg2, g_wg2);
    cudaGetSymbolAddress((void**)&wg3, g_wg3);
    cudaGetSymbolAddress((void**)&fcwr, g_fcwr);
    cudaGetSymbolAddress((void**)&w1s, g_w1s);

    // 1: all weight prep
    prep_kernel<<<1012, 256>>>(w1, w2_1, w3_1, w2_2, w3_2, fcw,
                               w1s, wg2, wg3, wp2, wp3, fcwr);

    // 2-4: stage 1 (pre-pooled conv1; bn select in profiled slot 4)
    conv1_kernel<<<dim3(8, BATCH), 256>>>(x, w1s, y1mx, y1mn);
    reduce_finalize_kernel<64><<<64, 256>>>(g1, 4096, 512 * 1024);
    bn_poolsel_sign4_f_kernel<<<(512 * 256 * 64 / 4 + 255) / 256, 256>>>(
        y1mx, y1mn, a1, b1, 512 * 256 * 64 / 4);

    // 5-9: stage 2
    conv_grp_kernel<16, 64><<<dim3(16, BATCH), 256>>>(a1, wg2, y2b, 8192);
    reduce_finalize_kernel<64><<<64, 256>>>(g2_1, 8192, 512 * 256);
    gemm64_kernel<<<(512 * 256) / 128, 256>>>(y2b, wp2, b2_1, y3mx, y3mn);
    reduce_finalize_kernel<256><<<256, 256>>>(g2_2, 1024, 512 * 256);
    bn_poolsel_sign4_i8_kernel<<<(512 * 64 * 256 / 4 + 255) / 256, 256>>>(
        y3mx, y3mn, a3, b2_2, 512 * 64 * 256 / 4);

    // 10-13: stage 3
    conv_grp_kernel<8, 256><<<dim3(8, BATCH), 256>>>(a3, wg3, y4b, 4096);
    reduce_finalize_kernel<256><<<256, 256>>>(g3_1, 4096, 512 * 64);
    gemm256_kernel<<<(512 * 64) / 64, 256>>>(y4b, wp3, b3_1, y5s);
    reduce_finalize_kernel<256><<<256, 256>>>(g3_2, 512, 512 * 64);

    // 14: FC (bn3_2 fused)
    fc_kernel<<<BATCH / FCB, 256>>>(y5s, fcwr, fcb, b3_2, out);
}

// round 12
// speedup vs baseline: 1.4839x; 1.0007x over previous
#include <cuda_runtime.h>
#include <cstdint>
#include <cstdio>

// ---------------------------------------------------------------------------
// LiBNet forward, batch 512.  Round 12 = Round 11 resubmit (infra flake).
// R10 (406us) + deterministic integer-atomic stats for the 4 integer stages;
// BN finalize inlined into fat consumers (gemm64 / gemm256 / fc). 11 launches.
// ---------------------------------------------------------------------------

#define BATCH 512

// Scratch (device globals)
__device__ float   g_y1mx[512u*256u*64u];  // conv1 window max [b,16,16,64]
__device__ float   g_y1mn[512u*256u*64u];  // conv1 window min
__device__ int8_t  g_a1[512u*256u*64u];    // sign(pool(bn1)) [b,16,16,64]
__device__ int8_t  g_y2b[512u*256u*64u];   // conv2_1 out int8
__device__ int8_t  g_y3mx[512u*64u*256u];  // gemm64 window max [b,8,8,256]
__device__ int8_t  g_y3mn[512u*64u*256u];  // gemm64 window min
__device__ int8_t  g_a3[512u*64u*256u];    // sign(pool(bn2_2)) [b,8,8,256]
__device__ int8_t  g_y4b[512u*64u*256u];   // conv3_1 out int8
__device__ int16_t g_y5s[512u*64u*256u];   // conv3_2 out int16
__device__ float   g_w1s[48*64];           // sign(w1) transposed [k][c]
__device__ int8_t  g_wg2[32*64];           // sign(w2_1) transposed [k][c]
__device__ int8_t  g_wg3[32*256];          // sign(w3_1) transposed [k][c]
__device__ int8_t  g_wp2[256*64];          // sign(w2_2)
__device__ int8_t  g_wp3[256*256];         // sign(w3_2)
__device__ float   g_part[2097152];        // float stats partials (conv1 only)
__device__ long long g_ll[4*512];          // int stats [stage][{sum,sq}][256]
__device__ float   g_mean[256];
__device__ float   g_scale[256];
__device__ float   g_fcwr[16384*10];       // fc_w n-major over NHWC-flatten

// stage bases in g_ll: sum at [c], sumsq at [256+c]
#define ST_GRP2   0
#define ST_GEMM64 1
#define ST_GRP3   2
#define ST_G256   3

__device__ __forceinline__ void atomAddLL(long long* p, long long v) {
    atomicAdd((unsigned long long*)p, (unsigned long long)v);
}

// shift-BN finalize for one channel from exact integer sums (fp64, same math
// as before: rint(log2(|inv|+1e-12)) clipped to +/-4).
__device__ __forceinline__ void finalize_channel(const long long* sbuf,
                                                 const float* gamma, int c,
                                                 double Pd, float* pm_out,
                                                 float* ps_out) {
    double mean = (double)sbuf[c] / Pd;
    double var  = (double)sbuf[256 + c] / Pd - mean * mean;
    double inv  = (double)gamma[c] / sqrt(var + 1e-5);
    double sh   = rint(log2(fabs(inv) + 1e-12));
    if (sh > 4.0) sh = 4.0;
    if (sh < -4.0) sh = -4.0;
    double sgn = (inv > 0.0) ? 1.0 : ((inv < 0.0) ? -1.0 : 0.0);
    *pm_out = (float)mean;
    *ps_out = (float)(sgn * exp2(sh));
}

// ---------------------------------------------------------------------------
// prep: all weight packing + zero the integer stat buffers.
// ---------------------------------------------------------------------------
__global__ void prep_kernel(const float* __restrict__ w1,
                            const float* __restrict__ w2_1,
                            const float* __restrict__ w3_1,
                            const float* __restrict__ w2_2,
                            const float* __restrict__ w3_2,
                            const float* __restrict__ fcw,
                            float* __restrict__ w1s,
                            int8_t* __restrict__ wg2,
                            int8_t* __restrict__ wg3,
                            int8_t* __restrict__ wp2,
                            int8_t* __restrict__ wp3,
                            float* __restrict__ fcwr,
                            long long* __restrict__ llbuf) {
    int bid = blockIdx.x, tid = threadIdx.x;
    if (bid < 640) {
        int i = bid * 256 + tid;  // fcwr: i = n*16384 + e, e = hw*256 + c
        int n = i / 16384;
        int e = i % 16384;
        int c = e & 255, hw = e >> 8;
        fcwr[i] = fcw[n * 16384 + c * 64 + hw];
    } else if (bid < 896) {
        int i = (bid - 640) * 256 + tid;
        float v = w3_2[i];
        wp3[i] = (int8_t)((v > 0.f) ? 1 : ((v < 0.f) ? -1 : 0));
    } else if (bid < 960) {
        int i = (bid - 896) * 256 + tid;
        float v = w2_2[i];
        wp2[i] = (int8_t)((v > 0.f) ? 1 : ((v < 0.f) ? -1 : 0));
    } else if (bid < 992) {
        int i = (bid - 960) * 256 + tid;  // i = k*256 + c
        int c = i & 255, k = i >> 8;
        float v = w3_1[c * 32 + k];
        wg3[i] = (int8_t)((v > 0.f) ? 1 : ((v < 0.f) ? -1 : 0));
    } else if (bid < 1000) {
        int i = (bid - 992) * 256 + tid;  // i = k*64 + c
        int c = i & 63, k = i >> 6;
        float v = w2_1[c * 32 + k];
        wg2[i] = (int8_t)((v > 0.f) ? 1 : ((v < 0.f) ? -1 : 0));
    } else if (bid < 1012) {
        int i = (bid - 1000) * 256 + tid;  // i = k*64 + c
        int c = i & 63, k = i >> 6;
        float v = w1[c * 48 + k];
        w1s[i] = (v > 0.f) ? 1.f : ((v < 0.f) ? -1.f : 0.f);
    } else {
        // zero the 4*512 long long stat accumulators
#pragma unroll
        for (int q = 0; q < 8; q++) llbuf[q * 256 + tid] = 0;
    }
}

// ---------------------------------------------------------------------------
// conv1: unchanged from R10 (float partials -> rf<64>).
// ---------------------------------------------------------------------------
__global__ void conv1_kernel(const float* __restrict__ x,
                             const float* __restrict__ w1s,
                             float* __restrict__ ymx,
                             float* __restrict__ ymn) {
    const int NS = 4096;
    int b = blockIdx.y, oy0 = blockIdx.x * 4;
    int tid = threadIdx.x;
    int c = tid & 63, xq = tid >> 6;

    __shared__ float xs[3][7][36];
    __shared__ float2 sred[256];

    for (int i = tid; i < 3 * 7 * 36; i += 256) {
        int col = i % 36;
        int r   = (i / 36) % 7;
        int ci  = i / 252;
        int ix = col - 1, iy = oy0 - 1 + r;
        float v = 0.f;
        if (ix >= 0 && ix < 32 && iy >= 0 && iy < 32)
            v = x[(((size_t)b * 3 + ci) * 32 + iy) * 32 + ix];
        xs[ci][r][col] = v;
    }

    float wr[48];
#pragma unroll
    for (int k = 0; k < 48; k++) wr[k] = w1s[k * 64 + c];
    __syncthreads();

    float s1 = 0.f, s2 = 0.f;
    float pmx[4], pmn[4];
#pragma unroll
    for (int r = 0; r < 4; r++) {
        float acc[8];
#pragma unroll
        for (int j = 0; j < 8; j++) acc[j] = 0.f;
#pragma unroll
        for (int ci = 0; ci < 3; ci++) {
#pragma unroll
            for (int kh = 0; kh < 4; kh++) {
                float rx[11];
#pragma unroll
                for (int t = 0; t < 11; t++) rx[t] = xs[ci][r + kh][xq * 8 + t];
#pragma unroll
                for (int kw = 0; kw < 4; kw++) {
                    float wv = wr[ci * 16 + kh * 4 + kw];
#pragma unroll
                    for (int j = 0; j < 8; j++) acc[j] += wv * rx[j + kw];
                }
            }
        }
#pragma unroll
        for (int j = 0; j < 8; j++) {
            s1 += acc[j];
            s2 += acc[j] * acc[j];
        }
        if ((r & 1) == 0) {
#pragma unroll
            for (int p = 0; p < 4; p++) {
                pmx[p] = fmaxf(acc[2 * p], acc[2 * p + 1]);
                pmn[p] = fminf(acc[2 * p], acc[2 * p + 1]);
            }
        } else {
            int poy = (oy0 >> 1) + (r >> 1);
#pragma unroll
            for (int p = 0; p < 4; p++) {
                float wmx = fmaxf(pmx[p], fmaxf(acc[2 * p], acc[2 * p + 1]));
                float wmn = fminf(pmn[p], fminf(acc[2 * p], acc[2 * p + 1]));
                size_t oi = (((size_t)b * 16 + poy) * 16 + xq * 4 + p) * 64 + c;
                ymx[oi] = wmx;
                ymn[oi] = wmn;
            }
        }
    }

    sred[tid] = make_float2(s1, s2);
    __syncthreads();
    if (tid < 64) {
        float2 a = sred[tid], b1 = sred[tid + 64], c1 = sred[tid + 128],
               d1 = sred[tid + 192];
        int slice = b * 8 + blockIdx.x;
        g_part[tid * NS + slice]        = a.x + b1.x + c1.x + d1.x;
        g_part[(64 + tid) * NS + slice] = a.y + b1.y + c1.y + d1.y;
    }
}

// rf for conv1 (float partials), writes g_mean/g_scale
template <int C>
__global__ void reduce_finalize_kernel(const float* __restrict__ gamma,
                                       int nslices, int P) {
    int c = blockIdx.x;
    int tid = threadIdx.x;
    float s1 = 0.f, s2 = 0.f;
    const float* p1 = g_part + (size_t)c * nslices;
    const float* p2 = g_part + (size_t)(C + c) * nslices;
#pragma unroll 4
    for (int s = tid; s < nslices; s += 256) {
        s1 += p1[s];
        s2 += p2[s];
    }
    __shared__ double sd1[256], sd2[256];
    sd1[tid] = (double)s1;
    sd2[tid] = (double)s2;
    __syncthreads();
    for (int s = 128; s > 0; s >>= 1) {
        if (tid < s) {
            sd1[tid] += sd1[tid + s];
            sd2[tid] += sd2[tid + s];
        }
        __syncthreads();
    }
    if (tid == 0) {
        double mean = sd1[0] / (double)P;
        double var  = sd2[0] / (double)P - mean * mean;
        double inv  = (double)gamma[c] / sqrt(var + 1e-5);
        double sh   = rint(log2(fabs(inv) + 1e-12));
        if (sh > 4.0) sh = 4.0;
        if (sh < -4.0) sh = -4.0;
        double sgn = (inv > 0.0) ? 1.0 : ((inv < 0.0) ? -1.0 : 0.0);
        g_mean[c]  = (float)mean;
        g_scale[c] = (float)(sgn * exp2(sh));
    }
}

// tiny finalize from integer sums -> g_mean/g_scale (for bn2_2 consumer)
__global__ void finalize_ll_kernel(const long long* __restrict__ sbuf,
                                   const float* __restrict__ gamma, int P) {
    int c = threadIdx.x;
    finalize_channel(sbuf, gamma, c, (double)P, &g_mean[c], &g_scale[c]);
}

// ---------------------------------------------------------------------------
// BN + pool-select + sign kernels (unchanged from R10).
// ---------------------------------------------------------------------------
__global__ void bn_poolsel_sign4_f_kernel(const float* __restrict__ ymx,
                                          const float* __restrict__ ymn,
                                          int8_t* __restrict__ out,
                                          const float* __restrict__ beta,
                                          int total4) {
    int idx = blockIdx.x * 256 + threadIdx.x;
    if (idx >= total4) return;
    int c = (idx * 4) & 63;
    float4 m  = *(const float4*)(g_mean + c);
    float4 s  = *(const float4*)(g_scale + c);
    float4 bt = *(const float4*)(beta + c);
    float4 vx = ((const float4*)ymx)[idx];
    float4 vn = ((const float4*)ymn)[idx];
    float v0 = (s.x > 0.f) ? vx.x : vn.x;
    float v1 = (s.y > 0.f) ? vx.y : vn.y;
    float v2 = (s.z > 0.f) ? vx.z : vn.z;
    float v3 = (s.w > 0.f) ? vx.w : vn.w;
    float r0 = (v0 - m.x) * s.x + bt.x;
    float r1 = (v1 - m.y) * s.y + bt.y;
    float r2 = (v2 - m.z) * s.z + bt.z;
    float r3 = (v3 - m.w) * s.w + bt.w;
    char4 o;
    o.x = (char)((r0 > 0.f) ? 1 : ((r0 < 0.f) ? -1 : 0));
    o.y = (char)((r1 > 0.f) ? 1 : ((r1 < 0.f) ? -1 : 0));
    o.z = (char)((r2 > 0.f) ? 1 : ((r2 < 0.f) ? -1 : 0));
    o.w = (char)((r3 > 0.f) ? 1 : ((r3 < 0.f) ? -1 : 0));
    ((char4*)out)[idx] = o;
}

__global__ void bn_poolsel_sign4_i8_kernel(const int8_t* __restrict__ ymx,
                                           const int8_t* __restrict__ ymn,
                                           int8_t* __restrict__ out,
                                           const float* __restrict__ beta,
                                           int total4) {
    int idx = blockIdx.x * 256 + threadIdx.x;
    if (idx >= total4) return;
    int c = (idx * 4) & 255;
    float4 m  = *(const float4*)(g_mean + c);
    float4 s  = *(const float4*)(g_scale + c);
    float4 bt = *(const float4*)(beta + c);
    char4 ux = ((const char4*)ymx)[idx];
    char4 un = ((const char4*)ymn)[idx];
    float v0 = (float)((s.x > 0.f) ? ux.x : un.x);
    float v1 = (float)((s.y > 0.f) ? ux.y : un.y);
    float v2 = (float)((s.z > 0.f) ? ux.z : un.z);
    float v3 = (float)((s.w > 0.f) ? ux.w : un.w);
    float r0 = (v0 - m.x) * s.x + bt.x;
    float r1 = (v1 - m.y) * s.y + bt.y;
    float r2 = (v2 - m.z) * s.z + bt.z;
    float r3 = (v3 - m.w) * s.w + bt.w;
    char4 o;
    o.x = (char)((r0 > 0.f) ? 1 : ((r0 < 0.f) ? -1 : 0));
    o.y = (char)((r1 > 0.f) ? 1 : ((r1 < 0.f) ? -1 : 0));
    o.z = (char)((r2 > 0.f) ? 1 : ((r2 < 0.f) ? -1 : 0));
    o.w = (char)((r3 > 0.f) ? 1 : ((r3 < 0.f) ? -1 : 0));
    ((char4*)out)[idx] = o;
}

// ---------------------------------------------------------------------------
// Grouped 4x4 binary conv: int16-pair LDS + dp4a; stats via ll atomics.
// ---------------------------------------------------------------------------
template <int H, int C>
__global__ void conv_grp_kernel(const int8_t* __restrict__ a,
                                const int8_t* __restrict__ wg,
                                int8_t* __restrict__ out,
                                long long* __restrict__ sbuf) {
    int b = blockIdx.y, oy = blockIdx.x;
    int tid = threadIdx.x;
    constexpr int PW = H + 3;
    __shared__ __align__(16) int8_t as[4][PW][C];
    __shared__ int2 sred[256];

    const int8_t* abase = a + (size_t)b * H * H * C;
    int total4 = (4 * PW * C) / 4;
    for (int i = tid; i < total4; i += 256) {
        int e = i * 4;
        int cc = e % C;
        int col = (e / C) % PW;
        int r = e / (C * PW);
        int ix = col - 1, iy = oy - 1 + r;
        int v = 0;
        if (ix >= 0 && ix < H && iy >= 0 && iy < H)
            v = *(const int*)(abase + ((size_t)iy * H + ix) * C + cc);
        *(int*)(&as[r][col][cc]) = v;
    }

    int c = tid % C;
    int xq = tid / C;
    int g2 = c & ~1;
    int wpair[16];
#pragma unroll
    for (int k = 0; k < 16; k++) {
        int w0 = (int)wg[k * C + c];
        int w1 = (int)wg[(16 + k) * C + c];
        wpair[k] = (w0 & 0xff) | ((w1 & 0xff) << 8);
    }
    __syncthreads();

    int is1 = 0, is2 = 0;
    constexpr int SPAN = (H * C) / 256;
    for (int j = 0; j < SPAN; j++) {
        int ox = xq * SPAN + j;
        int acc = 0;
#pragma unroll
        for (int kh = 0; kh < 4; kh++) {
#pragma unroll
            for (int kw = 0; kw < 4; kw++) {
                int v = (int)*(const uint16_t*)&as[kh][ox + kw][g2];
                acc = __dp4a(v, wpair[kh * 4 + kw], acc);
            }
        }
        out[(((size_t)b * H + oy) * H + ox) * C + c] = (int8_t)acc;
        is1 += acc;
        is2 += acc * acc;
    }

    if (C == 256) {
        atomAddLL(&sbuf[c], (long long)is1);
        atomAddLL(&sbuf[256 + c], (long long)is2);
    } else {
        sred[tid] = make_int2(is1, is2);
        __syncthreads();
        if (tid < C) {
            int a1 = 0, a2 = 0;
#pragma unroll
            for (int q = 0; q < 256 / C; q++) {
                a1 += sred[q * C + tid].x;
                a2 += sred[q * C + tid].y;
            }
            atomAddLL(&sbuf[tid], (long long)a1);
            atomAddLL(&sbuf[256 + tid], (long long)a2);
        }
    }
}

// ---------------------------------------------------------------------------
// gemm64: inline bn2_1 finalize from exact int sums; pre-pool (max,min) out;
// own stats via ll atomics.
// ---------------------------------------------------------------------------
__global__ void gemm64_kernel(const int8_t* __restrict__ yin,
                              const int8_t* __restrict__ wp,
                              const float* __restrict__ gamma,
                              const float* __restrict__ beta,
                              const long long* __restrict__ stat_in,
                              long long* __restrict__ stat_out,
                              int8_t* __restrict__ omx,
                              int8_t* __restrict__ omn) {
    __shared__ __align__(16) int as[128][16];
    __shared__ float pm[64], ps[64], pb[64];
    int tid = threadIdx.x;
    if (tid < 64) {
        finalize_channel(stat_in, gamma, tid, 131072.0, &pm[tid], &ps[tid]);
        pb[tid] = beta[tid];
    }
    int c = tid;
    int wr[16];
    const int* w4 = (const int*)wp + c * 16;
#pragma unroll
    for (int k = 0; k < 16; k++) wr[k] = w4[k];
    __syncthreads();

    size_t p0 = (size_t)blockIdx.x * 128;
    const int* y4 = (const int*)(yin + p0 * 64);
    for (int i = tid; i < 2048; i += 256) {
        int c0 = (i & 15) * 4;
        int v = y4[i];
        float r0 = ((float)(char)(v)       - pm[c0])     * ps[c0]     + pb[c0];
        float r1 = ((float)(char)(v >> 8)  - pm[c0 + 1]) * ps[c0 + 1] + pb[c0 + 1];
        float r2 = ((float)(char)(v >> 16) - pm[c0 + 2]) * ps[c0 + 2] + pb[c0 + 2];
        float r3 = ((float)(char)(v >> 24) - pm[c0 + 3]) * ps[c0 + 3] + pb[c0 + 3];
        int u0 = (r0 > 0.f) ? 1 : ((r0 < 0.f) ? -1 : 0);
        int u1 = (r1 > 0.f) ? 1 : ((r1 < 0.f) ? -1 : 0);
        int u2 = (r2 > 0.f) ? 1 : ((r2 < 0.f) ? -1 : 0);
        int u3 = (r3 > 0.f) ? 1 : ((r3 < 0.f) ? -1 : 0);
        as[i >> 4][i & 15] =
            (u0 & 0xff) | ((u1 & 0xff) << 8) | ((u2 & 0xff) << 16) | (u3 << 24);
    }
    __syncthreads();

    int bimg = blockIdx.x >> 1;
    int prow0 = (blockIdx.x & 1) * 4;
    int is1 = 0, is2 = 0;
    int rpx[8], rpn[8];
    for (int lr = 0; lr < 8; lr++) {
#pragma unroll
        for (int cp = 0; cp < 8; cp++) {
            int a0, a1;
#pragma unroll
            for (int h = 0; h < 2; h++) {
                int p = lr * 16 + cp * 2 + h;
                int acc = 0;
                const int4* av = (const int4*)as[p];
#pragma unroll
                for (int k4 = 0; k4 < 4; k4++) {
                    int4 v = av[k4];
                    acc = __dp4a(v.x, wr[k4 * 4 + 0], acc);
                    acc = __dp4a(v.y, wr[k4 * 4 + 1], acc);
                    acc = __dp4a(v.z, wr[k4 * 4 + 2], acc);
                    acc = __dp4a(v.w, wr[k4 * 4 + 3], acc);
                }
                is1 += acc;
                is2 += acc * acc;
                if (h == 0) a0 = acc; else a1 = acc;
            }
            int hx = max(a0, a1), hn = min(a0, a1);
            if ((lr & 1) == 0) {
                rpx[cp] = hx;
                rpn[cp] = hn;
            } else {
                int wmx = max(rpx[cp], hx);
                int wmn = min(rpn[cp], hn);
                size_t oi = (((size_t)bimg * 8 + prow0 + (lr >> 1)) * 8 + cp) * 256 + c;
                omx[oi] = (int8_t)wmx;
                omn[oi] = (int8_t)wmn;
            }
        }
    }
    atomAddLL(&stat_out[c], (long long)is1);
    atomAddLL(&stat_out[256 + c], (long long)is2);
}

// gemm256: inline bn3_1 finalize; own stats via ll atomics.
__global__ void gemm256_kernel(const int8_t* __restrict__ yin,
                               const int8_t* __restrict__ wp,
                               const float* __restrict__ gamma,
                               const float* __restrict__ beta,
                               const long long* __restrict__ stat_in,
                               long long* __restrict__ stat_out,
                               int16_t* __restrict__ out) {
    __shared__ __align__(16) int as[64][64];
    __shared__ float pm[256], ps[256], pb[256];
    int tid = threadIdx.x;
    finalize_channel(stat_in, gamma, tid, 32768.0, &pm[tid], &ps[tid]);
    pb[tid] = beta[tid];
    int c = tid;
    int wr[64];
    const int* w4 = (const int*)wp + c * 64;
#pragma unroll
    for (int k = 0; k < 64; k++) wr[k] = w4[k];
    __syncthreads();

    size_t p0 = (size_t)blockIdx.x * 64;
    const int* y4 = (const int*)(yin + p0 * 256);
    for (int i = tid; i < 4096; i += 256) {
        int c0 = (i & 63) * 4;
        int v = y4[i];
        float r0 = ((float)(char)(v)       - pm[c0])     * ps[c0]     + pb[c0];
        float r1 = ((float)(char)(v >> 8)  - pm[c0 + 1]) * ps[c0 + 1] + pb[c0 + 1];
        float r2 = ((float)(char)(v >> 16) - pm[c0 + 2]) * ps[c0 + 2] + pb[c0 + 2];
        float r3 = ((float)(char)(v >> 24) - pm[c0 + 3]) * ps[c0 + 3] + pb[c0 + 3];
        int u0 = (r0 > 0.f) ? 1 : ((r0 < 0.f) ? -1 : 0);
        int u1 = (r1 > 0.f) ? 1 : ((r1 < 0.f) ? -1 : 0);
        int u2 = (r2 > 0.f) ? 1 : ((r2 < 0.f) ? -1 : 0);
        int u3 = (r3 > 0.f) ? 1 : ((r3 < 0.f) ? -1 : 0);
        as[i >> 6][i & 63] =
            (u0 & 0xff) | ((u1 & 0xff) << 8) | ((u2 & 0xff) << 16) | (u3 << 24);
    }
    __syncthreads();

    int is1 = 0, is2 = 0;
    for (int p = 0; p < 64; p++) {
        int acc = 0;
        const int4* av = (const int4*)as[p];
#pragma unroll
        for (int k4 = 0; k4 < 16; k4++) {
            int4 v = av[k4];
            acc = __dp4a(v.x, wr[k4 * 4 + 0], acc);
            acc = __dp4a(v.y, wr[k4 * 4 + 1], acc);
            acc = __dp4a(v.z, wr[k4 * 4 + 2], acc);
            acc = __dp4a(v.w, wr[k4 * 4 + 3], acc);
        }
        out[(p0 + p) * 256 + c] = (int16_t)acc;
        is1 += acc;
        is2 += acc * acc;
    }
    atomAddLL(&stat_out[c], (long long)is1);
    atomAddLL(&stat_out[256 + c], (long long)is2);
}

// ---------------------------------------------------------------------------
// FC with inline bn3_2 finalize; 4 batches per block; int16 input.
// ---------------------------------------------------------------------------
#define FCB 4
__global__ void fc_kernel(const int16_t* __restrict__ y5,
                          const float* __restrict__ fcwr,
                          const float* __restrict__ fc_b,
                          const float* __restrict__ gamma,
                          const float* __restrict__ beta,
                          const long long* __restrict__ stat_in,
                          float* __restrict__ out) {
    __shared__ float pm[256], ps[256], pb[256];
    int b0 = blockIdx.x * FCB;
    int tid = threadIdx.x;
    finalize_channel(stat_in, gamma, tid, 32768.0, &pm[tid], &ps[tid]);
    pb[tid] = beta[tid];
    __syncthreads();

    float acc[FCB][10];
#pragma unroll
    for (int bb = 0; bb < FCB; bb++)
#pragma unroll
        for (int n = 0; n < 10; n++) acc[bb][n] = 0.f;

    for (int i = tid; i < 16384; i += 256) {
        int c = i & 255;
        float m = pm[c], s = ps[c], bt = pb[c];
        float w[10];
#pragma unroll
        for (int n = 0; n < 10; n++) w[n] = fcwr[n * 16384 + i];
#pragma unroll
        for (int bb = 0; bb < FCB; bb++) {
            float v = ((float)y5[(size_t)(b0 + bb) * 16384 + i] - m) * s + bt;
#pragma unroll
            for (int n = 0; n < 10; n++) acc[bb][n] += v * w[n];
        }
    }

    __shared__ float sred[8][FCB * 10];
    int lane = tid & 31, wid = tid >> 5;
#pragma unroll
    for (int bb = 0; bb < FCB; bb++)
#pragma unroll
        for (int n = 0; n < 10; n++) {
            float v = acc[bb][n];
#pragma unroll
            for (int o = 16; o > 0; o >>= 1)
                v += __shfl_xor_sync(0xffffffffu, v, o);
            if (lane == 0) sred[wid][bb * 10 + n] = v;
        }
    __syncthreads();
    if (tid < FCB * 10) {
        float v = 0.f;
#pragma unroll
        for (int w8 = 0; w8 < 8; w8++) v += sred[w8][tid];
        int bb = tid / 10, n = tid % 10;
        out[(b0 + bb) * 10 + n] = v + fc_b[n];
    }
}

// ---------------------------------------------------------------------------
extern "C" void kernel_launch(void* const* d_in, const int* in_sizes, int n_in,
                              void* d_out, int out_size) {
    const float* x    = (const float*)d_in[0];
    const float* w1   = (const float*)d_in[1];
    const float* g1   = (const float*)d_in[2];
    const float* b1   = (const float*)d_in[3];
    const float* w2_1 = (const float*)d_in[4];
    const float* g2_1 = (const float*)d_in[5];
    const float* b2_1 = (const float*)d_in[6];
    const float* w2_2 = (const float*)d_in[7];
    const float* g2_2 = (const float*)d_in[8];
    const float* b2_2 = (const float*)d_in[9];
    const float* w3_1 = (const float*)d_in[10];
    const float* g3_1 = (const float*)d_in[11];
    const float* b3_1 = (const float*)d_in[12];
    const float* w3_2 = (const float*)d_in[13];
    const float* g3_2 = (const float*)d_in[14];
    const float* b3_2 = (const float*)d_in[15];
    const float* fcw  = (const float*)d_in[16];
    const float* fcb  = (const float*)d_in[17];
    float* out = (float*)d_out;

    float *y1mx, *y1mn, *fcwr, *w1s;
    int8_t *a1, *a3, *y2b, *y3mx, *y3mn, *y4b, *wp2, *wp3, *wg2, *wg3;
    int16_t *y5s;
    long long* llb;
    cudaGetSymbolAddress((void**)&y1mx, g_y1mx);
    cudaGetSymbolAddress((void**)&y1mn, g_y1mn);
    cudaGetSymbolAddress((void**)&y2b, g_y2b);
    cudaGetSymbolAddress((void**)&y3mx, g_y3mx);
    cudaGetSymbolAddress((void**)&y3mn, g_y3mn);
    cudaGetSymbolAddress((void**)&y4b, g_y4b);
    cudaGetSymbolAddress((void**)&y5s, g_y5s);
    cudaGetSymbolAddress((void**)&a1, g_a1);
    cudaGetSymbolAddress((void**)&a3, g_a3);
    cudaGetSymbolAddress((void**)&wp2, g_wp2);
    cudaGetSymbolAddress((void**)&wp3, g_wp3);
    cudaGetSymbolAddress((void**)&wg2, g_wg2);
    cudaGetSymbolAddress((void**)&wg3, g_wg3);
    cudaGetSymbolAddress((void**)&fcwr, g_fcwr);
    cudaGetSymbolAddress((void**)&w1s, g_w1s);
    cudaGetSymbolAddress((void**)&llb, g_ll);

    // 1: weight prep + zero int stat buffers (re-zeroed every call -> graph-
    // replay deterministic)
    prep_kernel<<<1013, 256>>>(w1, w2_1, w3_1, w2_2, w3_2, fcw,
                               w1s, wg2, wg3, wp2, wp3, fcwr, llb);

    // 2-4: stage 1 (float stats path unchanged)
    conv1_kernel<<<dim3(8, BATCH), 256>>>(x, w1s, y1mx, y1mn);
    reduce_finalize_kernel<64><<<64, 256>>>(g1, 4096, 512 * 1024);
    bn_poolsel_sign4_f_kernel<<<(512 * 256 * 64 / 4 + 255) / 256, 256>>>(
        y1mx, y1mn, a1, b1, 512 * 256 * 64 / 4);

    // 5-8: stage 2 (grp2 stats -> gemm64 inline; gemm64 stats -> finalize_ll)
    conv_grp_kernel<16, 64><<<dim3(16, BATCH), 256>>>(a1, wg2, y2b,
                                                      llb + ST_GRP2 * 512);
    gemm64_kernel<<<(512 * 256) / 128, 256>>>(y2b, wp2, g2_1, b2_1,
                                              llb + ST_GRP2 * 512,
                                              llb + ST_GEMM64 * 512,
                                              y3mx, y3mn);
    finalize_ll_kernel<<<1, 256>>>(llb + ST_GEMM64 * 512, g2_2, 131072);
    bn_poolsel_sign4_i8_kernel<<<(512 * 64 * 256 / 4 + 255) / 256, 256>>>(
        y3mx, y3mn, a3, b2_2, 512 * 64 * 256 / 4);

    // 9-10: stage 3 (grp3 stats -> gemm256 inline)
    conv_grp_kernel<8, 256><<<dim3(8, BATCH), 256>>>(a3, wg3, y4b,
                                                     llb + ST_GRP3 * 512);
    gemm256_kernel<<<(512 * 64) / 64, 256>>>(y4b, wp3, g3_1, b3_1,
                                             llb + ST_GRP3 * 512,
                                             llb + ST_G256 * 512, y5s);

    // 11: FC (bn3_2 finalize inline)
    fc_kernel<<<BATCH / FCB, 256>>>(y5s, fcwr, fcb, g3_2, b3_2,
                                    llb + ST_G256 * 512, out);
}